// round 9
// baseline (speedup 1.0000x reference)
#include <cuda_runtime.h>
#include <cuda_fp16.h>
#include <cstdint>
#include <math.h>

// ---------------------------------------------------------------------------
// Problem constants
// ---------------------------------------------------------------------------
#define BB 2
#define TT 4096
#define DD 1024
#define FF 4096
#define SS 4096
#define BT (BB * TT)          // 8192
#define BTD ((size_t)BT * DD) // 8,388,608
#define BTF ((size_t)BT * FF) // 33,554,432
#define NC 64
#define CH 64
#define BDNC ((size_t)BB * DD * NC) // 131072

#define MM ((size_t)1048576)
#define WTOT (21 * MM)

// fp32 scratch
__device__ float g_scratch[4 * BTD + 2 * BDNC + BDNC + (size_t)BT * 4 + BTF];

#define OFF_XN   ((size_t)0)
#define OFF_Z    (OFF_XN + BTD)
#define OFF_HT   (OFF_Z + BTD)
#define OFF_X1   (OFF_HT + BTD)
#define OFF_SA   (OFF_X1 + BTD)
#define OFF_SB   (OFF_SA + BDNC)
#define OFF_HS   (OFF_SB + BDNC)
#define OFF_TV   (OFF_HS + BDNC)
#define OFF_TI   (OFF_TV + (size_t)BT * 2)

// fp16 pool
#define HOFF_MIX   ((size_t)0)
#define HOFF_WZ    (1 * MM)
#define HOFF_WH    (2 * MM)
#define HOFF_PQ    (3 * MM)
#define HOFF_PO    (4 * MM)
#define HOFF_SK    (5 * MM)
#define HOFF_GATE  (9 * MM)
#define HOFF_UP    (13 * MM)
#define HOFF_DOWN  (17 * MM)
#define HOFF_CONVH (21 * MM)
#define HOFF_XNH   (HOFF_CONVH + BTD)
#define HOFF_BIG2H (HOFF_XNH + BTD)
__device__ __half g_half[HOFF_BIG2H + BTF];

// ---------------------------------------------------------------------------
// One mega-cast: all 9 weight tensors fp32 -> fp16 pool
// ---------------------------------------------------------------------------
__global__ void __launch_bounds__(256) castall_kernel(
    const float* __restrict__ mix, const float* __restrict__ wz,
    const float* __restrict__ wh,  const float* __restrict__ pq,
    const float* __restrict__ po,  const float* __restrict__ sk,
    const float* __restrict__ gate,const float* __restrict__ up,
    const float* __restrict__ down, __half* __restrict__ dst)
{
    const size_t i = ((size_t)blockIdx.x * blockDim.x + threadIdx.x) * 4;
    if (i >= WTOT) return;
    const float* src; size_t base;
    if (i < 5 * MM) {
        switch (i >> 20) {
            case 0: src = mix; base = 0;      break;
            case 1: src = wz;  base = 1 * MM; break;
            case 2: src = wh;  base = 2 * MM; break;
            case 3: src = pq;  base = 3 * MM; break;
            default: src = po; base = 4 * MM; break;
        }
    } else if (i < 9 * MM)  { src = sk;   base = 5 * MM; }
    else if (i < 13 * MM)   { src = gate; base = 9 * MM; }
    else if (i < 17 * MM)   { src = up;   base = 13 * MM; }
    else                    { src = down; base = 17 * MM; }
    float4 v = *(const float4*)(src + (i - base));
    __half2 lo = __floats2half2_rn(v.x, v.y);
    __half2 hi = __floats2half2_rn(v.z, v.w);
    uint2 o = { *(unsigned*)&lo, *(unsigned*)&hi };
    *(uint2*)(dst + i) = o;
}

// ---------------------------------------------------------------------------
// RMSNorm (fp32 or fp16 out)
// ---------------------------------------------------------------------------
template <int HALF_OUT>
__global__ void __launch_bounds__(256) rmsnorm_kernel(
    const float* __restrict__ x, const float* __restrict__ w,
    float* __restrict__ out, __half* __restrict__ outh)
{
    const size_t row = blockIdx.x;
    const int tid = threadIdx.x;
    const float4* xr = (const float4*)(x + row * DD);
    float4 a = xr[tid];
    float ss = a.x * a.x + a.y * a.y + a.z * a.z + a.w * a.w;
    #pragma unroll
    for (int o = 16; o; o >>= 1) ss += __shfl_xor_sync(0xffffffffu, ss, o);
    __shared__ float wss[8];
    if ((tid & 31) == 0) wss[tid >> 5] = ss;
    __syncthreads();
    if (tid < 8) {
        float v = wss[tid];
        #pragma unroll
        for (int o = 4; o; o >>= 1) v += __shfl_xor_sync(0xffu, v, o);
        if (tid == 0) wss[0] = v;
    }
    __syncthreads();
    const float inv = rsqrtf(wss[0] * (1.0f / DD) + 1e-6f);
    float4 wv = ((const float4*)w)[tid];
    float4 o4;
    o4.x = a.x * wv.x * inv;
    o4.y = a.y * wv.y * inv;
    o4.z = a.z * wv.z * inv;
    o4.w = a.w * wv.w * inv;
    if (HALF_OUT) {
        __half2 lo = __floats2half2_rn(o4.x, o4.y);
        __half2 hi = __floats2half2_rn(o4.z, o4.w);
        uint2 u = { *(unsigned*)&lo, *(unsigned*)&hi };
        *(uint2*)(outh + row * DD + tid * 4) = u;
    } else {
        ((float4*)(out + row * DD))[tid] = o4;
    }
}

// ---------------------------------------------------------------------------
// Multi-scale causal depthwise conv -> fp16 out
// ---------------------------------------------------------------------------
__global__ void __launch_bounds__(256) conv_kernel(
    const float* __restrict__ xn,
    const float* __restrict__ w3, const float* __restrict__ w7,
    const float* __restrict__ w15, __half* __restrict__ out)
{
    const size_t idx = (size_t)blockIdx.x * blockDim.x + threadIdx.x;
    const int d = (int)(idx & (DD - 1));
    const size_t bt = idx / DD;
    const int t = (int)(bt & (TT - 1));
    const int b = (int)(bt / TT);
    const float* base = xn + (size_t)b * TT * DD + d;
    float acc = 0.0f;
    #pragma unroll
    for (int j = 0; j < 15; j++) {
        int tt = t - 14 + j;
        if (tt < 0) continue;
        float wsum = w15[d * 15 + j];
        if (j >= 8)  wsum += w7[d * 7 + (j - 8)];
        if (j >= 12) wsum += w3[d * 3 + (j - 12)];
        acc += wsum * base[(size_t)tt * DD];
    }
    out[idx] = __float2half_rn(acc);
}

// ---------------------------------------------------------------------------
// fp16 tensor GEMM: ldmatrix + mma.sync.m16n8k16.
// 128x128 CTA tile, 128 threads / 4 warps, warp tile 64x64 (high ILP,
// low LDSM:HMMA ratio), K-tile 64, 3-stage cp.async pipeline.
// ---------------------------------------------------------------------------
#define EPI_NONE    0
#define EPI_RESID   4
#define EPI_SILUMUL 5
#define EPI_GRU     6
#define EPI_TOP2    7

#define KTILE 64
#define LDTH 72
#define TILEH (128 * LDTH)
#define STAGEH (2 * TILEH)
#define CLD 132
#define SMEM_BYTES (3 * STAGEH * 2)        // 110592 B

__device__ __forceinline__ void cpasync16(unsigned saddr, const void* gptr) {
    asm volatile("cp.async.cg.shared.global [%0], [%1], 16;\n"
                 :: "r"(saddr), "l"(gptr));
}
__device__ __forceinline__ void ldsm_x4(unsigned* r, unsigned saddr) {
    asm volatile("ldmatrix.sync.aligned.m8n8.x4.shared.b16 {%0,%1,%2,%3}, [%4];"
                 : "=r"(r[0]), "=r"(r[1]), "=r"(r[2]), "=r"(r[3]) : "r"(saddr));
}
__device__ __forceinline__ void mma16816(
    float* d, const unsigned* a, unsigned b0, unsigned b1)
{
    asm volatile(
        "mma.sync.aligned.m16n8k16.row.col.f32.f16.f16.f32 "
        "{%0,%1,%2,%3}, {%4,%5,%6,%7}, {%8,%9}, {%0,%1,%2,%3};"
        : "+f"(d[0]), "+f"(d[1]), "+f"(d[2]), "+f"(d[3])
        : "r"(a[0]), "r"(a[1]), "r"(a[2]), "r"(a[3]), "r"(b0), "r"(b1));
}
__device__ __forceinline__ void top2_ins(float v, int i,
    float& v1, int& i1, float& v2, int& i2)
{
    if (v > v1 || (v == v1 && i < i1)) { v2 = v1; i2 = i1; v1 = v; i1 = i; }
    else if (v > v2 || (v == v2 && i < i2)) { v2 = v; i2 = i; }
}

template <int EPI, int HOUT>
__global__ void __launch_bounds__(128, 2) tgemm_kernel(
    const __half* __restrict__ A, const __half* __restrict__ W,
    void* __restrict__ Cout, const float* __restrict__ bias,
    const float* __restrict__ extraf, const __half* __restrict__ extrah,
    float* __restrict__ aux, int* __restrict__ auxi,
    int M, int N, int K, float scale)
{
    extern __shared__ __align__(16) char smem_raw[];
    __half* smem = (__half*)smem_raw;
    const int tid  = threadIdx.x;
    const int warp = tid >> 5;
    const int lid  = tid & 31;
    const int wm   = warp & 1;      // 64-row slice
    const int wn   = warp >> 1;     // 64-col slice
    const int bm   = blockIdx.y * 128;
    const int bn   = blockIdx.x * 128;

    unsigned sA[3], sB[3];
    #pragma unroll
    for (int s = 0; s < 3; s++) {
        sA[s] = (unsigned)__cvta_generic_to_shared(smem + s * STAGEH);
        sB[s] = sA[s] + TILEH * 2;
    }

    float acc[4][8][4];
    #pragma unroll
    for (int i = 0; i < 4; i++)
        #pragma unroll
        for (int j = 0; j < 8; j++)
            #pragma unroll
            for (int q = 0; q < 4; q++) acc[i][j][q] = 0.0f;

    const int KT = K / KTILE;

    auto load_tile = [&](int kt, int s) {
        const __half* Ag = A + (size_t)bm * K + kt * KTILE;
        const __half* Bg = W + (size_t)bn * K + kt * KTILE;
        #pragma unroll
        for (int j = 0; j < 8; j++) {
            const int i   = tid + (j << 7);
            const int row = i >> 3;
            const int seg = (i & 7) << 3;
            cpasync16(sA[s] + (unsigned)(row * LDTH + seg) * 2,
                      Ag + (size_t)row * K + seg);
            cpasync16(sB[s] + (unsigned)(row * LDTH + seg) * 2,
                      Bg + (size_t)row * K + seg);
        }
        asm volatile("cp.async.commit_group;\n");
    };

    const int lrow = lid & 15;
    const int lcol = (lid >> 4) << 3;

    load_tile(0, 0);
    load_tile(1, 1);

    for (int kt = 0; kt < KT; kt++) {
        if (kt == KT - 1) asm volatile("cp.async.wait_group 0;\n");
        else              asm volatile("cp.async.wait_group 1;\n");
        __syncthreads();
        // start next DMA before compute (target buffer freed by this barrier)
        if (kt + 2 < KT) load_tile(kt + 2, (kt + 2) % 3);

        const int s = kt % 3;
        const unsigned As = sA[s];
        const unsigned Bs = sB[s];
        #pragma unroll
        for (int kk = 0; kk < 4; kk++) {
            unsigned a[4][4], b[4][4];
            #pragma unroll
            for (int i = 0; i < 4; i++)
                ldsm_x4(a[i], As + (unsigned)((wm * 64 + i * 16 + lrow) * LDTH
                                              + kk * 16 + lcol) * 2);
            #pragma unroll
            for (int j = 0; j < 4; j++)
                ldsm_x4(b[j], Bs + (unsigned)((wn * 64 + j * 16 + lrow) * LDTH
                                              + kk * 16 + lcol) * 2);
            #pragma unroll
            for (int i = 0; i < 4; i++)
                #pragma unroll
                for (int j = 0; j < 4; j++) {
                    mma16816(acc[i][2 * j],     a[i], b[j][0], b[j][2]);
                    mma16816(acc[i][2 * j + 1], a[i], b[j][1], b[j][3]);
                }
        }
    }
    __syncthreads();

    // stage accumulators to smem (reuses pipeline buffers)
    float* Cs = (float*)smem_raw;   // 128 x CLD
    const int tr = lid >> 2;
    const int tc = (lid & 3) << 1;
    #pragma unroll
    for (int i = 0; i < 4; i++)
        #pragma unroll
        for (int j = 0; j < 8; j++) {
            float* p = Cs + (wm * 64 + i * 16 + tr) * CLD + wn * 64 + j * 8 + tc;
            p[0] = acc[i][j][0];
            p[1] = acc[i][j][1];
            p[8 * CLD + 0] = acc[i][j][2];
            p[8 * CLD + 1] = acc[i][j][3];
        }
    __syncthreads();

    // epilogue: each warp-iteration covers one row's 128 cols (4/lane)
    #pragma unroll 1
    for (int it = 0; it < 32; it++) {
        const int idx = tid + (it << 7);
        const int r = idx >> 5;
        const int c = (idx & 31) << 2;
        float4 v4 = *(const float4*)(Cs + r * CLD + c);
        float v[4] = { v4.x, v4.y, v4.z, v4.w };

        if (EPI == EPI_TOP2) {
            float v1 = -3.4e38f, v2 = -3.4e38f;
            int i1 = 0x7fffffff, i2 = 0x7fffffff;
            #pragma unroll
            for (int q = 0; q < 4; q++)
                top2_ins(v[q] * scale, bn + c + q, v1, i1, v2, i2);
            #pragma unroll
            for (int o = 16; o; o >>= 1) {
                float ov1 = __shfl_xor_sync(0xffffffffu, v1, o);
                float ov2 = __shfl_xor_sync(0xffffffffu, v2, o);
                int   oi1 = __shfl_xor_sync(0xffffffffu, i1, o);
                int   oi2 = __shfl_xor_sync(0xffffffffu, i2, o);
                top2_ins(ov1, oi1, v1, i1, v2, i2);
                top2_ins(ov2, oi2, v1, i1, v2, i2);
            }
            if (lid == 0) {
                const size_t cb = (size_t)(bm + r) * 64 + blockIdx.x * 2;
                aux[cb]  = v1;  aux[cb + 1]  = v2;
                auxi[cb] = i1;  auxi[cb + 1] = i2;
            }
            continue;
        }

        const size_t off = (size_t)(bm + r) * N + bn + c;
        if (EPI == EPI_GRU) {
            const int cg = bn + c;
            if (cg < DD) {
                float4 bv = *(const float4*)(bias + cg);
                float4 o4;
                o4.x = 1.0f / (1.0f + expf(-(v[0] + bv.x)));
                o4.y = 1.0f / (1.0f + expf(-(v[1] + bv.y)));
                o4.z = 1.0f / (1.0f + expf(-(v[2] + bv.z)));
                o4.w = 1.0f / (1.0f + expf(-(v[3] + bv.w)));
                *(float4*)((float*)Cout + (size_t)(bm + r) * DD + cg) = o4;
            } else {
                float4 bv = *(const float4*)(extraf + cg - DD);
                float4 o4 = { v[0] + bv.x, v[1] + bv.y, v[2] + bv.z, v[3] + bv.w };
                *(float4*)(aux + (size_t)(bm + r) * DD + cg - DD) = o4;
            }
            continue;
        }

        if (EPI == EPI_RESID) {
            float4 ev = *(const float4*)(extraf + off);
            v[0] += ev.x; v[1] += ev.y; v[2] += ev.z; v[3] += ev.w;
        } else if (EPI == EPI_SILUMUL) {
            uint2 eu = *(const uint2*)(extrah + off);
            __half2 e0 = *(__half2*)&eu.x;
            __half2 e1 = *(__half2*)&eu.y;
            float g0 = __low2float(e0), g1 = __high2float(e0);
            float g2 = __low2float(e1), g3 = __high2float(e1);
            v[0] *= g0 / (1.0f + expf(-g0));
            v[1] *= g1 / (1.0f + expf(-g1));
            v[2] *= g2 / (1.0f + expf(-g2));
            v[3] *= g3 / (1.0f + expf(-g3));
        }

        if (HOUT) {
            __half2 lo = __floats2half2_rn(v[0], v[1]);
            __half2 hi = __floats2half2_rn(v[2], v[3]);
            uint2 u = { *(unsigned*)&lo, *(unsigned*)&hi };
            *(uint2*)((__half*)Cout + off) = u;
        } else {
            float4 o4 = { v[0], v[1], v[2], v[3] };
            *(float4*)((float*)Cout + off) = o4;
        }
    }
}

// ---------------------------------------------------------------------------
// Final top-2 over 64 candidates per row
// ---------------------------------------------------------------------------
__global__ void __launch_bounds__(256) top2final_kernel(
    const float* __restrict__ cval, const int* __restrict__ cidx,
    float* __restrict__ topv, int* __restrict__ topi)
{
    const int row = blockIdx.x * 8 + (threadIdx.x >> 5);
    const int lid = threadIdx.x & 31;
    const size_t base = (size_t)row * 64 + lid * 2;
    float v1 = cval[base], v2 = cval[base + 1];
    int   i1 = cidx[base], i2 = cidx[base + 1];
    if (v2 > v1 || (v2 == v1 && i2 < i1)) {
        float tv = v1; v1 = v2; v2 = tv;
        int ti = i1; i1 = i2; i2 = ti;
    }
    #pragma unroll
    for (int o = 16; o; o >>= 1) {
        float ov1 = __shfl_xor_sync(0xffffffffu, v1, o);
        float ov2 = __shfl_xor_sync(0xffffffffu, v2, o);
        int   oi1 = __shfl_xor_sync(0xffffffffu, i1, o);
        int   oi2 = __shfl_xor_sync(0xffffffffu, i2, o);
        top2_ins(ov1, oi1, v1, i1, v2, i2);
        top2_ins(ov2, oi2, v1, i1, v2, i2);
    }
    if (lid == 0) {
        topv[row * 2 + 0] = v1;
        topv[row * 2 + 1] = v2;
        topi[row * 2 + 0] = i1;
        topi[row * 2 + 1] = i2;
    }
}

// ---------------------------------------------------------------------------
// MinGRU chunked scan (3 passes)
// ---------------------------------------------------------------------------
__global__ void __launch_bounds__(256) scan1_kernel(
    const float* __restrict__ z, const float* __restrict__ ht,
    float* __restrict__ Aout, float* __restrict__ Bout)
{
    const int tid = blockIdx.x * blockDim.x + threadIdx.x;
    const int d = tid & (DD - 1);
    const int r = tid / DD;
    const int c = r & (NC - 1);
    const int b = r / NC;
    const size_t base = ((size_t)b * TT + (size_t)c * CH) * DD + d;
    float Aa = 1.0f, Bb = 0.0f;
    #pragma unroll 4
    for (int t = 0; t < CH; t++) {
        const float zt = z[base + (size_t)t * DD];
        const float hh = ht[base + (size_t)t * DD];
        const float a = 1.0f - zt;
        Bb = a * Bb + zt * hh;
        Aa *= a;
    }
    Aout[tid] = Aa;
    Bout[tid] = Bb;
}

__global__ void __launch_bounds__(256) scan2_kernel(
    const float* __restrict__ h_prev, const float* __restrict__ Ain,
    const float* __restrict__ Bin, float* __restrict__ hstart,
    float* __restrict__ hlast)
{
    const int tid = blockIdx.x * blockDim.x + threadIdx.x;
    if (tid >= BB * DD) return;
    const int d = tid & (DD - 1);
    const int b = tid / DD;
    float h = h_prev[tid];
    for (int c = 0; c < NC; c++) {
        const size_t i = ((size_t)b * NC + c) * DD + d;
        hstart[i] = h;
        h = Ain[i] * h + Bin[i];
    }
    hlast[tid] = h;
}

__global__ void __launch_bounds__(256) scan3_kernel(
    const float* __restrict__ z, const float* __restrict__ ht,
    const float* __restrict__ hstart, float* __restrict__ xout)
{
    const int tid = blockIdx.x * blockDim.x + threadIdx.x;
    const int d = tid & (DD - 1);
    const int r = tid / DD;
    const int c = r & (NC - 1);
    const int b = r / NC;
    const size_t base = ((size_t)b * TT + (size_t)c * CH) * DD + d;
    float h = hstart[tid];
    for (int t = 0; t < CH; t++) {
        const float zt = z[base + (size_t)t * DD];
        const float hh = ht[base + (size_t)t * DD];
        h = (1.0f - zt) * h + zt * hh;
        xout[base + (size_t)t * DD] += h;
    }
}

// retrieved -> fp16 out
__global__ void __launch_bounds__(256) gather_kernel(
    const float* __restrict__ topv, const int* __restrict__ topi,
    const float* __restrict__ V, __half* __restrict__ out)
{
    const size_t idx = (size_t)blockIdx.x * blockDim.x + threadIdx.x;
    const int d = (int)(idx & (DD - 1));
    const size_t row = idx / DD;
    const float v1 = topv[row * 2 + 0];
    const float v2 = topv[row * 2 + 1];
    const int i1 = topi[row * 2 + 0];
    const int i2 = topi[row * 2 + 1];
    const float e = expf(v2 - v1);
    const float inv = 1.0f / (1.0f + e);
    const float w1 = inv, w2 = e * inv;
    out[idx] = __float2half_rn(
        w1 * V[(size_t)i1 * DD + d] + w2 * V[(size_t)i2 * DD + d]);
}

// ---------------------------------------------------------------------------
// Launch sequence
// ---------------------------------------------------------------------------
extern "C" void kernel_launch(void* const* d_in, const int* in_sizes, int n_in,
                              void* d_out, int out_size)
{
    (void)in_sizes; (void)n_in; (void)out_size;
    const float* x        = (const float*)d_in[0];
    const float* h_prev   = (const float*)d_in[1];
    const float* norm1_w  = (const float*)d_in[2];
    const float* conv3_w  = (const float*)d_in[3];
    const float* conv7_w  = (const float*)d_in[4];
    const float* conv15_w = (const float*)d_in[5];
    const float* mix_w    = (const float*)d_in[6];
    const float* norm2_w  = (const float*)d_in[7];
    const float* Wz_w     = (const float*)d_in[8];
    const float* Wz_b     = (const float*)d_in[9];
    const float* Wh_w     = (const float*)d_in[10];
    const float* Wh_b     = (const float*)d_in[11];
    const float* norm3_w  = (const float*)d_in[12];
    const float* slot_k   = (const float*)d_in[13];
    const float* slot_v   = (const float*)d_in[14];
    const float* projq_w  = (const float*)d_in[15];
    const float* projout_w= (const float*)d_in[16];
    const float* norm4_w  = (const float*)d_in[17];
    const float* gate_w   = (const float*)d_in[18];
    const float* up_w     = (const float*)d_in[19];
    const float* down_w   = (const float*)d_in[20];
    float* out = (float*)d_out;

    float* scr = nullptr;
    cudaGetSymbolAddress((void**)&scr, g_scratch);
    __half* hp = nullptr;
    cudaGetSymbolAddress((void**)&hp, g_half);

    float* xn    = scr + OFF_XN;
    float* zbuf  = scr + OFF_Z;
    float* htbuf = scr + OFF_HT;
    float* scanA = scr + OFF_SA;
    float* scanB = scr + OFF_SB;
    float* hstart= scr + OFF_HS;
    float* topv  = scr + OFF_TV;
    int*   topi  = (int*)(scr + OFF_TI);

    __half* mixh  = hp + HOFF_MIX;
    __half* Wzh   = hp + HOFF_WZ;
    __half* pqh   = hp + HOFF_PQ;
    __half* poh   = hp + HOFF_PO;
    __half* skh   = hp + HOFF_SK;
    __half* gateh = hp + HOFF_GATE;
    __half* uph   = hp + HOFF_UP;
    __half* downh = hp + HOFF_DOWN;
    __half* convh = hp + HOFF_CONVH;
    __half* xnh   = hp + HOFF_XNH;
    __half* big2h = hp + HOFF_BIG2H;

    cudaFuncSetAttribute(tgemm_kernel<EPI_RESID,0>,   cudaFuncAttributeMaxDynamicSharedMemorySize, SMEM_BYTES);
    cudaFuncSetAttribute(tgemm_kernel<EPI_GRU,0>,     cudaFuncAttributeMaxDynamicSharedMemorySize, SMEM_BYTES);
    cudaFuncSetAttribute(tgemm_kernel<EPI_NONE,1>,    cudaFuncAttributeMaxDynamicSharedMemorySize, SMEM_BYTES);
    cudaFuncSetAttribute(tgemm_kernel<EPI_TOP2,0>,    cudaFuncAttributeMaxDynamicSharedMemorySize, SMEM_BYTES);
    cudaFuncSetAttribute(tgemm_kernel<EPI_SILUMUL,1>, cudaFuncAttributeMaxDynamicSharedMemorySize, SMEM_BYTES);

    const dim3 blk(256);
    const dim3 gblk(128);
    const dim3 gD(DD / 128, BT / 128);
    const dim3 gG(2048 / 128, BT / 128);
    const dim3 gF(FF / 128, BT / 128);
    const dim3 gS(SS / 128, BT / 128);

    castall_kernel<<<(unsigned)(WTOT / 1024), blk>>>(
        mix_w, Wz_w, Wh_w, projq_w, projout_w, slot_k, gate_w, up_w, down_w, hp);

    // 1. conv block
    rmsnorm_kernel<0><<<BT, blk>>>(x, norm1_w, xn, nullptr);
    conv_kernel<<<(unsigned)(BTD / 256), blk>>>(xn, conv3_w, conv7_w, conv15_w, convh);
    tgemm_kernel<EPI_RESID,0><<<gD, gblk, SMEM_BYTES>>>(
        convh, mixh, out, nullptr, x, nullptr, nullptr, nullptr, BT, DD, DD, 1.0f);

    // 2. MinGRU (fused Wz+Wh GEMM)
    rmsnorm_kernel<1><<<BT, blk>>>(out, norm2_w, nullptr, xnh);
    tgemm_kernel<EPI_GRU,0><<<gG, gblk, SMEM_BYTES>>>(
        xnh, Wzh, zbuf, Wz_b, Wh_b, nullptr, htbuf, nullptr, BT, 2048, DD, 1.0f);
    scan1_kernel<<<(unsigned)(BDNC / 256), blk>>>(zbuf, htbuf, scanA, scanB);
    scan2_kernel<<<(BB * DD + 255) / 256, blk>>>(h_prev, scanA, scanB, hstart, out + BTD);
    scan3_kernel<<<(unsigned)(BDNC / 256), blk>>>(zbuf, htbuf, hstart, out);

    // 3. slot memory (top2 fused into scores GEMM epilogue)
    rmsnorm_kernel<1><<<BT, blk>>>(out, norm3_w, nullptr, xnh);
    tgemm_kernel<EPI_NONE,1><<<gD, gblk, SMEM_BYTES>>>(
        xnh, pqh, convh, nullptr, nullptr, nullptr, nullptr, nullptr, BT, DD, DD, 1.0f);
    tgemm_kernel<EPI_TOP2,0><<<gS, gblk, SMEM_BYTES>>>(
        convh, skh, nullptr, nullptr, nullptr, nullptr, zbuf, (int*)htbuf,
        BT, SS, DD, 0.03125f);
    top2final_kernel<<<BT / 8, blk>>>(zbuf, (int*)htbuf, topv, topi);
    gather_kernel<<<(unsigned)(BTD / 256), blk>>>(topv, topi, slot_v, xnh);
    tgemm_kernel<EPI_RESID,0><<<gD, gblk, SMEM_BYTES>>>(
        xnh, poh, out, nullptr, out, nullptr, nullptr, nullptr, BT, DD, DD, 1.0f);

    // 4. SwiGLU FFN
    rmsnorm_kernel<1><<<BT, blk>>>(out, norm4_w, nullptr, convh);
    tgemm_kernel<EPI_NONE,1><<<gF, gblk, SMEM_BYTES>>>(
        convh, gateh, big2h, nullptr, nullptr, nullptr, nullptr, nullptr, BT, FF, DD, 1.0f);
    tgemm_kernel<EPI_SILUMUL,1><<<gF, gblk, SMEM_BYTES>>>(
        convh, uph, big2h, nullptr, nullptr, big2h, nullptr, nullptr, BT, FF, DD, 1.0f);
    tgemm_kernel<EPI_RESID,0><<<gD, gblk, SMEM_BYTES>>>(
        big2h, downh, out, nullptr, out, nullptr, nullptr, nullptr, BT, DD, FF, 1.0f);
}

// round 11
// speedup vs baseline: 1.0249x; 1.0249x over previous
#include <cuda_runtime.h>
#include <cuda_fp16.h>
#include <cstdint>
#include <math.h>

// ---------------------------------------------------------------------------
// Problem constants
// ---------------------------------------------------------------------------
#define BB 2
#define TT 4096
#define DD 1024
#define FF 4096
#define SS 4096
#define BT (BB * TT)          // 8192
#define BTD ((size_t)BT * DD) // 8,388,608
#define BTF ((size_t)BT * FF) // 33,554,432
#define NC 64
#define CH 64
#define BDNC ((size_t)BB * DD * NC) // 131072

#define MM ((size_t)1048576)
#define WTOT (21 * MM)

// fp32 scratch
__device__ float g_scratch[4 * BTD + 2 * BDNC + BDNC + (size_t)BT * 4 + BTF];

#define OFF_XN   ((size_t)0)
#define OFF_Z    (OFF_XN + BTD)
#define OFF_HT   (OFF_Z + BTD)
#define OFF_X1   (OFF_HT + BTD)
#define OFF_SA   (OFF_X1 + BTD)
#define OFF_SB   (OFF_SA + BDNC)
#define OFF_HS   (OFF_SB + BDNC)
#define OFF_TV   (OFF_HS + BDNC)
#define OFF_TI   (OFF_TV + (size_t)BT * 2)

// fp16 pool
#define HOFF_MIX   ((size_t)0)
#define HOFF_WZ    (1 * MM)
#define HOFF_WH    (2 * MM)
#define HOFF_PQ    (3 * MM)
#define HOFF_PO    (4 * MM)
#define HOFF_SK    (5 * MM)
#define HOFF_GATE  (9 * MM)
#define HOFF_UP    (13 * MM)
#define HOFF_DOWN  (17 * MM)
#define HOFF_CONVH (21 * MM)
#define HOFF_XNH   (HOFF_CONVH + BTD)
#define HOFF_BIG2H (HOFF_XNH + BTD)
__device__ __half g_half[HOFF_BIG2H + BTF];

// ---------------------------------------------------------------------------
// One mega-cast: all 9 weight tensors fp32 -> fp16 pool
// ---------------------------------------------------------------------------
__global__ void __launch_bounds__(256) castall_kernel(
    const float* __restrict__ mix, const float* __restrict__ wz,
    const float* __restrict__ wh,  const float* __restrict__ pq,
    const float* __restrict__ po,  const float* __restrict__ sk,
    const float* __restrict__ gate,const float* __restrict__ up,
    const float* __restrict__ down, __half* __restrict__ dst)
{
    const size_t i = ((size_t)blockIdx.x * blockDim.x + threadIdx.x) * 4;
    if (i >= WTOT) return;
    const float* src; size_t base;
    if (i < 5 * MM) {
        switch (i >> 20) {
            case 0: src = mix; base = 0;      break;
            case 1: src = wz;  base = 1 * MM; break;
            case 2: src = wh;  base = 2 * MM; break;
            case 3: src = pq;  base = 3 * MM; break;
            default: src = po; base = 4 * MM; break;
        }
    } else if (i < 9 * MM)  { src = sk;   base = 5 * MM; }
    else if (i < 13 * MM)   { src = gate; base = 9 * MM; }
    else if (i < 17 * MM)   { src = up;   base = 13 * MM; }
    else                    { src = down; base = 17 * MM; }
    float4 v = *(const float4*)(src + (i - base));
    __half2 lo = __floats2half2_rn(v.x, v.y);
    __half2 hi = __floats2half2_rn(v.z, v.w);
    uint2 o = { *(unsigned*)&lo, *(unsigned*)&hi };
    *(uint2*)(dst + i) = o;
}

// ---------------------------------------------------------------------------
// RMSNorm (fp32 or fp16 out)
// ---------------------------------------------------------------------------
template <int HALF_OUT>
__global__ void __launch_bounds__(256) rmsnorm_kernel(
    const float* __restrict__ x, const float* __restrict__ w,
    float* __restrict__ out, __half* __restrict__ outh)
{
    const size_t row = blockIdx.x;
    const int tid = threadIdx.x;
    const float4* xr = (const float4*)(x + row * DD);
    float4 a = xr[tid];
    float ss = a.x * a.x + a.y * a.y + a.z * a.z + a.w * a.w;
    #pragma unroll
    for (int o = 16; o; o >>= 1) ss += __shfl_xor_sync(0xffffffffu, ss, o);
    __shared__ float wss[8];
    if ((tid & 31) == 0) wss[tid >> 5] = ss;
    __syncthreads();
    if (tid < 8) {
        float v = wss[tid];
        #pragma unroll
        for (int o = 4; o; o >>= 1) v += __shfl_xor_sync(0xffu, v, o);
        if (tid == 0) wss[0] = v;
    }
    __syncthreads();
    const float inv = rsqrtf(wss[0] * (1.0f / DD) + 1e-6f);
    float4 wv = ((const float4*)w)[tid];
    float4 o4;
    o4.x = a.x * wv.x * inv;
    o4.y = a.y * wv.y * inv;
    o4.z = a.z * wv.z * inv;
    o4.w = a.w * wv.w * inv;
    if (HALF_OUT) {
        __half2 lo = __floats2half2_rn(o4.x, o4.y);
        __half2 hi = __floats2half2_rn(o4.z, o4.w);
        uint2 u = { *(unsigned*)&lo, *(unsigned*)&hi };
        *(uint2*)(outh + row * DD + tid * 4) = u;
    } else {
        ((float4*)(out + row * DD))[tid] = o4;
    }
}

// ---------------------------------------------------------------------------
// Multi-scale causal depthwise conv -> fp16 out
// ---------------------------------------------------------------------------
__global__ void __launch_bounds__(256) conv_kernel(
    const float* __restrict__ xn,
    const float* __restrict__ w3, const float* __restrict__ w7,
    const float* __restrict__ w15, __half* __restrict__ out)
{
    const size_t idx = (size_t)blockIdx.x * blockDim.x + threadIdx.x;
    const int d = (int)(idx & (DD - 1));
    const size_t bt = idx / DD;
    const int t = (int)(bt & (TT - 1));
    const int b = (int)(bt / TT);
    const float* base = xn + (size_t)b * TT * DD + d;
    float acc = 0.0f;
    #pragma unroll
    for (int j = 0; j < 15; j++) {
        int tt = t - 14 + j;
        if (tt < 0) continue;
        float wsum = w15[d * 15 + j];
        if (j >= 8)  wsum += w7[d * 7 + (j - 8)];
        if (j >= 12) wsum += w3[d * 3 + (j - 12)];
        acc += wsum * base[(size_t)tt * DD];
    }
    out[idx] = __float2half_rn(acc);
}

// ---------------------------------------------------------------------------
// fp16 tensor GEMM: ldmatrix + mma.sync.m16n8k16.
// 128x128 CTA tile, 256 threads / 8 warps, warp tile 32x64 (R8 config),
// K-tile 32, 5-stage cp.async ring with wait_group 3 (deep latency cover).
// ---------------------------------------------------------------------------
#define EPI_NONE    0
#define EPI_RESID   4
#define EPI_SILUMUL 5
#define EPI_GRU     6
#define EPI_TOP2    7

#define KTILE 32
#define LDTH 40                            // 32 + 8 pad halves -> 80B stride
#define TILEH (128 * LDTH)
#define STAGEH (2 * TILEH)
#define NSTAGE 5
#define CLD 132
#define SMEM_BYTES (NSTAGE * STAGEH * 2)   // 102400 B (>= 128*CLD*4 = 67584)

__device__ __forceinline__ void cpasync16(unsigned saddr, const void* gptr) {
    asm volatile("cp.async.cg.shared.global [%0], [%1], 16;\n"
                 :: "r"(saddr), "l"(gptr));
}
__device__ __forceinline__ void ldsm_x4(unsigned* r, unsigned saddr) {
    asm volatile("ldmatrix.sync.aligned.m8n8.x4.shared.b16 {%0,%1,%2,%3}, [%4];"
                 : "=r"(r[0]), "=r"(r[1]), "=r"(r[2]), "=r"(r[3]) : "r"(saddr));
}
__device__ __forceinline__ void mma16816(
    float* d, const unsigned* a, unsigned b0, unsigned b1)
{
    asm volatile(
        "mma.sync.aligned.m16n8k16.row.col.f32.f16.f16.f32 "
        "{%0,%1,%2,%3}, {%4,%5,%6,%7}, {%8,%9}, {%0,%1,%2,%3};"
        : "+f"(d[0]), "+f"(d[1]), "+f"(d[2]), "+f"(d[3])
        : "r"(a[0]), "r"(a[1]), "r"(a[2]), "r"(a[3]), "r"(b0), "r"(b1));
}
__device__ __forceinline__ void top2_ins(float v, int i,
    float& v1, int& i1, float& v2, int& i2)
{
    if (v > v1 || (v == v1 && i < i1)) { v2 = v1; i2 = i1; v1 = v; i1 = i; }
    else if (v > v2 || (v == v2 && i < i2)) { v2 = v; i2 = i; }
}

template <int EPI, int HOUT>
__global__ void __launch_bounds__(256, 2) tgemm_kernel(
    const __half* __restrict__ A, const __half* __restrict__ W,
    void* __restrict__ Cout, const float* __restrict__ bias,
    const float* __restrict__ extraf, const __half* __restrict__ extrah,
    float* __restrict__ aux, int* __restrict__ auxi,
    int M, int N, int K, float scale)
{
    extern __shared__ __align__(16) char smem_raw[];
    __half* smem = (__half*)smem_raw;
    const int tid  = threadIdx.x;
    const int warp = tid >> 5;
    const int lid  = tid & 31;
    const int wm   = warp & 3;      // 32-row slice
    const int wn   = warp >> 2;     // 64-col slice
    const int bm   = blockIdx.y * 128;
    const int bn   = blockIdx.x * 128;

    unsigned sA[NSTAGE], sB[NSTAGE];
    #pragma unroll
    for (int s = 0; s < NSTAGE; s++) {
        sA[s] = (unsigned)__cvta_generic_to_shared(smem + s * STAGEH);
        sB[s] = sA[s] + TILEH * 2;
    }

    float acc[2][8][4];
    #pragma unroll
    for (int i = 0; i < 2; i++)
        #pragma unroll
        for (int j = 0; j < 8; j++)
            #pragma unroll
            for (int q = 0; q < 4; q++) acc[i][j][q] = 0.0f;

    const int KT = K / KTILE;

    // per K-tile: A/B each 128 rows x 64B = 512 16B-chunks; 256 threads -> 2 each
    auto load_tile = [&](int kt, int s) {
        const __half* Ag = A + (size_t)bm * K + kt * KTILE;
        const __half* Bg = W + (size_t)bn * K + kt * KTILE;
        #pragma unroll
        for (int j = 0; j < 2; j++) {
            const int i   = tid + (j << 8);
            const int row = i >> 2;
            const int seg = (i & 3) << 3;
            cpasync16(sA[s] + (unsigned)(row * LDTH + seg) * 2,
                      Ag + (size_t)row * K + seg);
            cpasync16(sB[s] + (unsigned)(row * LDTH + seg) * 2,
                      Bg + (size_t)row * K + seg);
        }
        asm volatile("cp.async.commit_group;\n");
    };

    const int lrow = lid & 15;
    const int lcol = (lid >> 4) << 3;

    load_tile(0, 0);
    load_tile(1, 1);
    load_tile(2, 2);
    load_tile(3, 3);

    for (int kt = 0; kt < KT; kt++) {
        asm volatile("cp.async.wait_group 3;\n");
        __syncthreads();
        // one commit per iteration keeps the outstanding-group count invariant
        if (kt + 4 < KT) load_tile(kt + 4, (kt + 4) % NSTAGE);
        else             asm volatile("cp.async.commit_group;\n");

        const int s = kt % NSTAGE;
        const unsigned As = sA[s];
        const unsigned Bs = sB[s];
        #pragma unroll
        for (int kk = 0; kk < 2; kk++) {
            unsigned a[2][4], b[4][4];
            #pragma unroll
            for (int i = 0; i < 2; i++)
                ldsm_x4(a[i], As + (unsigned)((wm * 32 + i * 16 + lrow) * LDTH
                                              + kk * 16 + lcol) * 2);
            #pragma unroll
            for (int j = 0; j < 4; j++)
                ldsm_x4(b[j], Bs + (unsigned)((wn * 64 + j * 16 + lrow) * LDTH
                                              + kk * 16 + lcol) * 2);
            #pragma unroll
            for (int i = 0; i < 2; i++)
                #pragma unroll
                for (int j = 0; j < 4; j++) {
                    mma16816(acc[i][2 * j],     a[i], b[j][0], b[j][2]);
                    mma16816(acc[i][2 * j + 1], a[i], b[j][1], b[j][3]);
                }
        }
    }
    __syncthreads();

    // stage accumulators to smem (reuses pipeline buffers)
    float* Cs = (float*)smem_raw;   // 128 x CLD
    const int tr = lid >> 2;
    const int tc = (lid & 3) << 1;
    #pragma unroll
    for (int i = 0; i < 2; i++)
        #pragma unroll
        for (int j = 0; j < 8; j++) {
            float* p = Cs + (wm * 32 + i * 16 + tr) * CLD + wn * 64 + j * 8 + tc;
            p[0] = acc[i][j][0];
            p[1] = acc[i][j][1];
            p[8 * CLD + 0] = acc[i][j][2];
            p[8 * CLD + 1] = acc[i][j][3];
        }
    __syncthreads();

    #pragma unroll 1
    for (int it = 0; it < 16; it++) {
        const int idx = tid + (it << 8);
        const int r = idx >> 5;
        const int c = (idx & 31) << 2;
        float4 v4 = *(const float4*)(Cs + r * CLD + c);
        float v[4] = { v4.x, v4.y, v4.z, v4.w };

        if (EPI == EPI_TOP2) {
            float v1 = -3.4e38f, v2 = -3.4e38f;
            int i1 = 0x7fffffff, i2 = 0x7fffffff;
            #pragma unroll
            for (int q = 0; q < 4; q++)
                top2_ins(v[q] * scale, bn + c + q, v1, i1, v2, i2);
            #pragma unroll
            for (int o = 16; o; o >>= 1) {
                float ov1 = __shfl_xor_sync(0xffffffffu, v1, o);
                float ov2 = __shfl_xor_sync(0xffffffffu, v2, o);
                int   oi1 = __shfl_xor_sync(0xffffffffu, i1, o);
                int   oi2 = __shfl_xor_sync(0xffffffffu, i2, o);
                top2_ins(ov1, oi1, v1, i1, v2, i2);
                top2_ins(ov2, oi2, v1, i1, v2, i2);
            }
            if (lid == 0) {
                const size_t cb = (size_t)(bm + r) * 64 + blockIdx.x * 2;
                aux[cb]  = v1;  aux[cb + 1]  = v2;
                auxi[cb] = i1;  auxi[cb + 1] = i2;
            }
            continue;
        }

        const size_t off = (size_t)(bm + r) * N + bn + c;
        if (EPI == EPI_GRU) {
            const int cg = bn + c;
            if (cg < DD) {
                float4 bv = *(const float4*)(bias + cg);
                float4 o4;
                o4.x = 1.0f / (1.0f + expf(-(v[0] + bv.x)));
                o4.y = 1.0f / (1.0f + expf(-(v[1] + bv.y)));
                o4.z = 1.0f / (1.0f + expf(-(v[2] + bv.z)));
                o4.w = 1.0f / (1.0f + expf(-(v[3] + bv.w)));
                *(float4*)((float*)Cout + (size_t)(bm + r) * DD + cg) = o4;
            } else {
                float4 bv = *(const float4*)(extraf + cg - DD);
                float4 o4 = { v[0] + bv.x, v[1] + bv.y, v[2] + bv.z, v[3] + bv.w };
                *(float4*)(aux + (size_t)(bm + r) * DD + cg - DD) = o4;
            }
            continue;
        }

        if (EPI == EPI_RESID) {
            float4 ev = *(const float4*)(extraf + off);
            v[0] += ev.x; v[1] += ev.y; v[2] += ev.z; v[3] += ev.w;
        } else if (EPI == EPI_SILUMUL) {
            uint2 eu = *(const uint2*)(extrah + off);
            __half2 e0 = *(__half2*)&eu.x;
            __half2 e1 = *(__half2*)&eu.y;
            float g0 = __low2float(e0), g1 = __high2float(e0);
            float g2 = __low2float(e1), g3 = __high2float(e1);
            v[0] *= g0 / (1.0f + expf(-g0));
            v[1] *= g1 / (1.0f + expf(-g1));
            v[2] *= g2 / (1.0f + expf(-g2));
            v[3] *= g3 / (1.0f + expf(-g3));
        }

        if (HOUT) {
            __half2 lo = __floats2half2_rn(v[0], v[1]);
            __half2 hi = __floats2half2_rn(v[2], v[3]);
            uint2 u = { *(unsigned*)&lo, *(unsigned*)&hi };
            *(uint2*)((__half*)Cout + off) = u;
        } else {
            float4 o4 = { v[0], v[1], v[2], v[3] };
            *(float4*)((float*)Cout + off) = o4;
        }
    }
}

// ---------------------------------------------------------------------------
// Fused: final top-2 over 64 candidates + softmax + gather (one block per row)
// ---------------------------------------------------------------------------
__global__ void __launch_bounds__(256) gather2_kernel(
    const float* __restrict__ cval, const int* __restrict__ cidx,
    const float* __restrict__ V, __half* __restrict__ out)
{
    const int row = blockIdx.x;
    const int tid = threadIdx.x;
    __shared__ float sw1, sw2;
    __shared__ int sidx1, sidx2;
    if (tid < 32) {
        const size_t base = (size_t)row * 64 + tid * 2;
        float v1 = cval[base], v2 = cval[base + 1];   // v1 >= v2 per epilogue
        int   i1 = cidx[base], i2 = cidx[base + 1];
        #pragma unroll
        for (int o = 16; o; o >>= 1) {
            float ov1 = __shfl_xor_sync(0xffffffffu, v1, o);
            float ov2 = __shfl_xor_sync(0xffffffffu, v2, o);
            int   oi1 = __shfl_xor_sync(0xffffffffu, i1, o);
            int   oi2 = __shfl_xor_sync(0xffffffffu, i2, o);
            top2_ins(ov1, oi1, v1, i1, v2, i2);
            top2_ins(ov2, oi2, v1, i1, v2, i2);
        }
        if (tid == 0) {
            const float e = expf(v2 - v1);
            const float inv = 1.0f / (1.0f + e);
            sw1 = inv; sw2 = e * inv; sidx1 = i1; sidx2 = i2;
        }
    }
    __syncthreads();
    const float w1 = sw1, w2 = sw2;
    const float4 a = ((const float4*)(V + (size_t)sidx1 * DD))[tid];
    const float4 b = ((const float4*)(V + (size_t)sidx2 * DD))[tid];
    __half2 lo = __floats2half2_rn(w1 * a.x + w2 * b.x, w1 * a.y + w2 * b.y);
    __half2 hi = __floats2half2_rn(w1 * a.z + w2 * b.z, w1 * a.w + w2 * b.w);
    uint2 u = { *(unsigned*)&lo, *(unsigned*)&hi };
    *(uint2*)(out + (size_t)row * DD + tid * 4) = u;
}

// ---------------------------------------------------------------------------
// MinGRU chunked scan (3 passes)
// ---------------------------------------------------------------------------
__global__ void __launch_bounds__(256) scan1_kernel(
    const float* __restrict__ z, const float* __restrict__ ht,
    float* __restrict__ Aout, float* __restrict__ Bout)
{
    const int tid = blockIdx.x * blockDim.x + threadIdx.x;
    const int d = tid & (DD - 1);
    const int r = tid / DD;
    const int c = r & (NC - 1);
    const int b = r / NC;
    const size_t base = ((size_t)b * TT + (size_t)c * CH) * DD + d;
    float Aa = 1.0f, Bb = 0.0f;
    #pragma unroll 4
    for (int t = 0; t < CH; t++) {
        const float zt = z[base + (size_t)t * DD];
        const float hh = ht[base + (size_t)t * DD];
        const float a = 1.0f - zt;
        Bb = a * Bb + zt * hh;
        Aa *= a;
    }
    Aout[tid] = Aa;
    Bout[tid] = Bb;
}

__global__ void __launch_bounds__(256) scan2_kernel(
    const float* __restrict__ h_prev, const float* __restrict__ Ain,
    const float* __restrict__ Bin, float* __restrict__ hstart,
    float* __restrict__ hlast)
{
    const int tid = blockIdx.x * blockDim.x + threadIdx.x;
    if (tid >= BB * DD) return;
    const int d = tid & (DD - 1);
    const int b = tid / DD;
    float h = h_prev[tid];
    for (int c = 0; c < NC; c++) {
        const size_t i = ((size_t)b * NC + c) * DD + d;
        hstart[i] = h;
        h = Ain[i] * h + Bin[i];
    }
    hlast[tid] = h;
}

__global__ void __launch_bounds__(256) scan3_kernel(
    const float* __restrict__ z, const float* __restrict__ ht,
    const float* __restrict__ hstart, float* __restrict__ xout)
{
    const int tid = blockIdx.x * blockDim.x + threadIdx.x;
    const int d = tid & (DD - 1);
    const int r = tid / DD;
    const int c = r & (NC - 1);
    const int b = r / NC;
    const size_t base = ((size_t)b * TT + (size_t)c * CH) * DD + d;
    float h = hstart[tid];
    for (int t = 0; t < CH; t++) {
        const float zt = z[base + (size_t)t * DD];
        const float hh = ht[base + (size_t)t * DD];
        h = (1.0f - zt) * h + zt * hh;
        xout[base + (size_t)t * DD] += h;
    }
}

// ---------------------------------------------------------------------------
// Launch sequence
// ---------------------------------------------------------------------------
extern "C" void kernel_launch(void* const* d_in, const int* in_sizes, int n_in,
                              void* d_out, int out_size)
{
    (void)in_sizes; (void)n_in; (void)out_size;
    const float* x        = (const float*)d_in[0];
    const float* h_prev   = (const float*)d_in[1];
    const float* norm1_w  = (const float*)d_in[2];
    const float* conv3_w  = (const float*)d_in[3];
    const float* conv7_w  = (const float*)d_in[4];
    const float* conv15_w = (const float*)d_in[5];
    const float* mix_w    = (const float*)d_in[6];
    const float* norm2_w  = (const float*)d_in[7];
    const float* Wz_w     = (const float*)d_in[8];
    const float* Wz_b     = (const float*)d_in[9];
    const float* Wh_w     = (const float*)d_in[10];
    const float* Wh_b     = (const float*)d_in[11];
    const float* norm3_w  = (const float*)d_in[12];
    const float* slot_k   = (const float*)d_in[13];
    const float* slot_v   = (const float*)d_in[14];
    const float* projq_w  = (const float*)d_in[15];
    const float* projout_w= (const float*)d_in[16];
    const float* norm4_w  = (const float*)d_in[17];
    const float* gate_w   = (const float*)d_in[18];
    const float* up_w     = (const float*)d_in[19];
    const float* down_w   = (const float*)d_in[20];
    float* out = (float*)d_out;

    float* scr = nullptr;
    cudaGetSymbolAddress((void**)&scr, g_scratch);
    __half* hp = nullptr;
    cudaGetSymbolAddress((void**)&hp, g_half);

    float* xn    = scr + OFF_XN;
    float* zbuf  = scr + OFF_Z;
    float* htbuf = scr + OFF_HT;
    float* scanA = scr + OFF_SA;
    float* scanB = scr + OFF_SB;
    float* hstart= scr + OFF_HS;

    __half* mixh  = hp + HOFF_MIX;
    __half* Wzh   = hp + HOFF_WZ;
    __half* pqh   = hp + HOFF_PQ;
    __half* poh   = hp + HOFF_PO;
    __half* skh   = hp + HOFF_SK;
    __half* gateh = hp + HOFF_GATE;
    __half* uph   = hp + HOFF_UP;
    __half* downh = hp + HOFF_DOWN;
    __half* convh = hp + HOFF_CONVH;
    __half* xnh   = hp + HOFF_XNH;
    __half* big2h = hp + HOFF_BIG2H;

    cudaFuncSetAttribute(tgemm_kernel<EPI_RESID,0>,   cudaFuncAttributeMaxDynamicSharedMemorySize, SMEM_BYTES);
    cudaFuncSetAttribute(tgemm_kernel<EPI_GRU,0>,     cudaFuncAttributeMaxDynamicSharedMemorySize, SMEM_BYTES);
    cudaFuncSetAttribute(tgemm_kernel<EPI_NONE,1>,    cudaFuncAttributeMaxDynamicSharedMemorySize, SMEM_BYTES);
    cudaFuncSetAttribute(tgemm_kernel<EPI_TOP2,0>,    cudaFuncAttributeMaxDynamicSharedMemorySize, SMEM_BYTES);
    cudaFuncSetAttribute(tgemm_kernel<EPI_SILUMUL,1>, cudaFuncAttributeMaxDynamicSharedMemorySize, SMEM_BYTES);

    const dim3 blk(256);
    const dim3 gD(DD / 128, BT / 128);
    const dim3 gG(2048 / 128, BT / 128);
    const dim3 gF(FF / 128, BT / 128);
    const dim3 gS(SS / 128, BT / 128);

    castall_kernel<<<(unsigned)(WTOT / 1024), blk>>>(
        mix_w, Wz_w, Wh_w, projq_w, projout_w, slot_k, gate_w, up_w, down_w, hp);

    // 1. conv block
    rmsnorm_kernel<0><<<BT, blk>>>(x, norm1_w, xn, nullptr);
    conv_kernel<<<(unsigned)(BTD / 256), blk>>>(xn, conv3_w, conv7_w, conv15_w, convh);
    tgemm_kernel<EPI_RESID,0><<<gD, blk, SMEM_BYTES>>>(
        convh, mixh, out, nullptr, x, nullptr, nullptr, nullptr, BT, DD, DD, 1.0f);

    // 2. MinGRU (fused Wz+Wh GEMM)
    rmsnorm_kernel<1><<<BT, blk>>>(out, norm2_w, nullptr, xnh);
    tgemm_kernel<EPI_GRU,0><<<gG, blk, SMEM_BYTES>>>(
        xnh, Wzh, zbuf, Wz_b, Wh_b, nullptr, htbuf, nullptr, BT, 2048, DD, 1.0f);
    scan1_kernel<<<(unsigned)(BDNC / 256), blk>>>(zbuf, htbuf, scanA, scanB);
    scan2_kernel<<<(BB * DD + 255) / 256, blk>>>(h_prev, scanA, scanB, hstart, out + BTD);
    scan3_kernel<<<(unsigned)(BDNC / 256), blk>>>(zbuf, htbuf, hstart, out);

    // 3. slot memory (top2 fused into scores GEMM epilogue; fused gather)
    rmsnorm_kernel<1><<<BT, blk>>>(out, norm3_w, nullptr, xnh);
    tgemm_kernel<EPI_NONE,1><<<gD, blk, SMEM_BYTES>>>(
        xnh, pqh, convh, nullptr, nullptr, nullptr, nullptr, nullptr, BT, DD, DD, 1.0f);
    tgemm_kernel<EPI_TOP2,0><<<gS, blk, SMEM_BYTES>>>(
        convh, skh, nullptr, nullptr, nullptr, nullptr, zbuf, (int*)htbuf,
        BT, SS, DD, 0.03125f);
    gather2_kernel<<<BT, blk>>>(zbuf, (int*)htbuf, slot_v, xnh);
    tgemm_kernel<EPI_RESID,0><<<gD, blk, SMEM_BYTES>>>(
        xnh, poh, out, nullptr, out, nullptr, nullptr, nullptr, BT, DD, DD, 1.0f);

    // 4. SwiGLU FFN
    rmsnorm_kernel<1><<<BT, blk>>>(out, norm4_w, nullptr, convh);
    tgemm_kernel<EPI_NONE,1><<<gF, blk, SMEM_BYTES>>>(
        convh, gateh, big2h, nullptr, nullptr, nullptr, nullptr, nullptr, BT, FF, DD, 1.0f);
    tgemm_kernel<EPI_SILUMUL,1><<<gF, blk, SMEM_BYTES>>>(
        convh, uph, big2h, nullptr, nullptr, big2h, nullptr, nullptr, BT, FF, DD, 1.0f);
    tgemm_kernel<EPI_RESID,0><<<gD, blk, SMEM_BYTES>>>(
        big2h, downh, out, nullptr, out, nullptr, nullptr, nullptr, BT, DD, FF, 1.0f);
}

// round 12
// speedup vs baseline: 1.1777x; 1.1492x over previous
#include <cuda_runtime.h>
#include <cuda_fp16.h>
#include <cstdint>
#include <math.h>

// ---------------------------------------------------------------------------
// Problem constants
// ---------------------------------------------------------------------------
#define BB 2
#define TT 4096
#define DD 1024
#define FF 4096
#define SS 4096
#define BT (BB * TT)          // 8192
#define BTD ((size_t)BT * DD) // 8,388,608
#define BTF ((size_t)BT * FF) // 33,554,432
#define NC 64
#define CH 64
#define BDNC ((size_t)BB * DD * NC) // 131072

#define MM ((size_t)1048576)
#define WTOT (21 * MM)

// fp32 scratch
__device__ float g_scratch[4 * BTD + 2 * BDNC + BDNC + (size_t)BT * 4 + BTF];

#define OFF_XN   ((size_t)0)
#define OFF_Z    (OFF_XN + BTD)
#define OFF_HT   (OFF_Z + BTD)
#define OFF_X1   (OFF_HT + BTD)
#define OFF_SA   (OFF_X1 + BTD)
#define OFF_SB   (OFF_SA + BDNC)
#define OFF_HS   (OFF_SB + BDNC)
#define OFF_TV   (OFF_HS + BDNC)
#define OFF_TI   (OFF_TV + (size_t)BT * 2)

// fp16 pool
#define HOFF_MIX   ((size_t)0)
#define HOFF_WZ    (1 * MM)
#define HOFF_WH    (2 * MM)
#define HOFF_PQ    (3 * MM)
#define HOFF_PO    (4 * MM)
#define HOFF_SK    (5 * MM)
#define HOFF_GATE  (9 * MM)
#define HOFF_UP    (13 * MM)
#define HOFF_DOWN  (17 * MM)
#define HOFF_CONVH (21 * MM)
#define HOFF_XNH   (HOFF_CONVH + BTD)
#define HOFF_BIG2H (HOFF_XNH + BTD)
__device__ __half g_half[HOFF_BIG2H + BTF];

// ---------------------------------------------------------------------------
// One mega-cast: all 9 weight tensors fp32 -> fp16 pool
// ---------------------------------------------------------------------------
__global__ void __launch_bounds__(256) castall_kernel(
    const float* __restrict__ mix, const float* __restrict__ wz,
    const float* __restrict__ wh,  const float* __restrict__ pq,
    const float* __restrict__ po,  const float* __restrict__ sk,
    const float* __restrict__ gate,const float* __restrict__ up,
    const float* __restrict__ down, __half* __restrict__ dst)
{
    const size_t i = ((size_t)blockIdx.x * blockDim.x + threadIdx.x) * 4;
    if (i >= WTOT) return;
    const float* src; size_t base;
    if (i < 5 * MM) {
        switch (i >> 20) {
            case 0: src = mix; base = 0;      break;
            case 1: src = wz;  base = 1 * MM; break;
            case 2: src = wh;  base = 2 * MM; break;
            case 3: src = pq;  base = 3 * MM; break;
            default: src = po; base = 4 * MM; break;
        }
    } else if (i < 9 * MM)  { src = sk;   base = 5 * MM; }
    else if (i < 13 * MM)   { src = gate; base = 9 * MM; }
    else if (i < 17 * MM)   { src = up;   base = 13 * MM; }
    else                    { src = down; base = 17 * MM; }
    float4 v = *(const float4*)(src + (i - base));
    __half2 lo = __floats2half2_rn(v.x, v.y);
    __half2 hi = __floats2half2_rn(v.z, v.w);
    uint2 o = { *(unsigned*)&lo, *(unsigned*)&hi };
    *(uint2*)(dst + i) = o;
}

// ---------------------------------------------------------------------------
// RMSNorm (fp32 or fp16 out)
// ---------------------------------------------------------------------------
template <int HALF_OUT>
__global__ void __launch_bounds__(256) rmsnorm_kernel(
    const float* __restrict__ x, const float* __restrict__ w,
    float* __restrict__ out, __half* __restrict__ outh)
{
    const size_t row = blockIdx.x;
    const int tid = threadIdx.x;
    const float4* xr = (const float4*)(x + row * DD);
    float4 a = xr[tid];
    float ss = a.x * a.x + a.y * a.y + a.z * a.z + a.w * a.w;
    #pragma unroll
    for (int o = 16; o; o >>= 1) ss += __shfl_xor_sync(0xffffffffu, ss, o);
    __shared__ float wss[8];
    if ((tid & 31) == 0) wss[tid >> 5] = ss;
    __syncthreads();
    if (tid < 8) {
        float v = wss[tid];
        #pragma unroll
        for (int o = 4; o; o >>= 1) v += __shfl_xor_sync(0xffu, v, o);
        if (tid == 0) wss[0] = v;
    }
    __syncthreads();
    const float inv = rsqrtf(wss[0] * (1.0f / DD) + 1e-6f);
    float4 wv = ((const float4*)w)[tid];
    float4 o4;
    o4.x = a.x * wv.x * inv;
    o4.y = a.y * wv.y * inv;
    o4.z = a.z * wv.z * inv;
    o4.w = a.w * wv.w * inv;
    if (HALF_OUT) {
        __half2 lo = __floats2half2_rn(o4.x, o4.y);
        __half2 hi = __floats2half2_rn(o4.z, o4.w);
        uint2 u = { *(unsigned*)&lo, *(unsigned*)&hi };
        *(uint2*)(outh + row * DD + tid * 4) = u;
    } else {
        ((float4*)(out + row * DD))[tid] = o4;
    }
}

// ---------------------------------------------------------------------------
// Multi-scale causal depthwise conv -> fp16 out
// ---------------------------------------------------------------------------
__global__ void __launch_bounds__(256) conv_kernel(
    const float* __restrict__ xn,
    const float* __restrict__ w3, const float* __restrict__ w7,
    const float* __restrict__ w15, __half* __restrict__ out)
{
    const size_t idx = (size_t)blockIdx.x * blockDim.x + threadIdx.x;
    const int d = (int)(idx & (DD - 1));
    const size_t bt = idx / DD;
    const int t = (int)(bt & (TT - 1));
    const int b = (int)(bt / TT);
    const float* base = xn + (size_t)b * TT * DD + d;
    float acc = 0.0f;
    #pragma unroll
    for (int j = 0; j < 15; j++) {
        int tt = t - 14 + j;
        if (tt < 0) continue;
        float wsum = w15[d * 15 + j];
        if (j >= 8)  wsum += w7[d * 7 + (j - 8)];
        if (j >= 12) wsum += w3[d * 3 + (j - 12)];
        acc += wsum * base[(size_t)tt * DD];
    }
    out[idx] = __float2half_rn(acc);
}

// ---------------------------------------------------------------------------
// fp16 tensor GEMM: ldmatrix + mma.sync.m16n8k16.
// R8 shape (128x128 CTA tile, 256 threads, warp tile 32x64, KTILE 64,
// 3-stage cp.async) but with ONE barrier per K-iteration.
// ---------------------------------------------------------------------------
#define EPI_NONE    0
#define EPI_RESID   4
#define EPI_SILUMUL 5
#define EPI_GRU     6
#define EPI_TOP2    7

#define KTILE 64
#define LDTH 72
#define TILEH (128 * LDTH)
#define STAGEH (2 * TILEH)
#define CLD 132
#define SMEM_BYTES (3 * STAGEH * 2)        // 110592 B

__device__ __forceinline__ void cpasync16(unsigned saddr, const void* gptr) {
    asm volatile("cp.async.cg.shared.global [%0], [%1], 16;\n"
                 :: "r"(saddr), "l"(gptr));
}
__device__ __forceinline__ void ldsm_x4(unsigned* r, unsigned saddr) {
    asm volatile("ldmatrix.sync.aligned.m8n8.x4.shared.b16 {%0,%1,%2,%3}, [%4];"
                 : "=r"(r[0]), "=r"(r[1]), "=r"(r[2]), "=r"(r[3]) : "r"(saddr));
}
__device__ __forceinline__ void mma16816(
    float* d, const unsigned* a, unsigned b0, unsigned b1)
{
    asm volatile(
        "mma.sync.aligned.m16n8k16.row.col.f32.f16.f16.f32 "
        "{%0,%1,%2,%3}, {%4,%5,%6,%7}, {%8,%9}, {%0,%1,%2,%3};"
        : "+f"(d[0]), "+f"(d[1]), "+f"(d[2]), "+f"(d[3])
        : "r"(a[0]), "r"(a[1]), "r"(a[2]), "r"(a[3]), "r"(b0), "r"(b1));
}
__device__ __forceinline__ void top2_ins(float v, int i,
    float& v1, int& i1, float& v2, int& i2)
{
    if (v > v1 || (v == v1 && i < i1)) { v2 = v1; i2 = i1; v1 = v; i1 = i; }
    else if (v > v2 || (v == v2 && i < i2)) { v2 = v; i2 = i; }
}

template <int EPI, int HOUT>
__global__ void __launch_bounds__(256, 2) tgemm_kernel(
    const __half* __restrict__ A, const __half* __restrict__ W,
    void* __restrict__ Cout, const float* __restrict__ bias,
    const float* __restrict__ extraf, const __half* __restrict__ extrah,
    float* __restrict__ aux, int* __restrict__ auxi,
    int M, int N, int K, float scale)
{
    extern __shared__ __align__(16) char smem_raw[];
    __half* smem = (__half*)smem_raw;
    const int tid  = threadIdx.x;
    const int warp = tid >> 5;
    const int lid  = tid & 31;
    const int wm   = warp & 3;      // 32-row slice
    const int wn   = warp >> 2;     // 64-col slice
    const int bm   = blockIdx.y * 128;
    const int bn   = blockIdx.x * 128;

    unsigned sA[3], sB[3];
    #pragma unroll
    for (int s = 0; s < 3; s++) {
        sA[s] = (unsigned)__cvta_generic_to_shared(smem + s * STAGEH);
        sB[s] = sA[s] + TILEH * 2;
    }

    float acc[2][8][4];
    #pragma unroll
    for (int i = 0; i < 2; i++)
        #pragma unroll
        for (int j = 0; j < 8; j++)
            #pragma unroll
            for (int q = 0; q < 4; q++) acc[i][j][q] = 0.0f;

    const int KT = K / KTILE;

    auto load_tile = [&](int kt, int s) {
        const __half* Ag = A + (size_t)bm * K + kt * KTILE;
        const __half* Bg = W + (size_t)bn * K + kt * KTILE;
        #pragma unroll
        for (int j = 0; j < 4; j++) {
            const int i   = tid + (j << 8);
            const int row = i >> 3;
            const int seg = (i & 7) << 3;
            cpasync16(sA[s] + (unsigned)(row * LDTH + seg) * 2,
                      Ag + (size_t)row * K + seg);
            cpasync16(sB[s] + (unsigned)(row * LDTH + seg) * 2,
                      Bg + (size_t)row * K + seg);
        }
        asm volatile("cp.async.commit_group;\n");
    };

    const int lrow = lid & 15;
    const int lcol = (lid >> 4) << 3;

    load_tile(0, 0);
    load_tile(1, 1);

    for (int kt = 0; kt < KT; kt++) {
        if (kt == KT - 1) asm volatile("cp.async.wait_group 0;\n");
        else              asm volatile("cp.async.wait_group 1;\n");
        __syncthreads();
        // single barrier per iter: stage (kt+2)%3 was consumed in iter kt-1,
        // and every warp passed this barrier only after finishing iter kt-1.
        if (kt + 2 < KT) load_tile(kt + 2, (kt + 2) % 3);

        const int s = kt % 3;
        const unsigned As = sA[s];
        const unsigned Bs = sB[s];
        #pragma unroll
        for (int kk = 0; kk < 4; kk++) {
            unsigned a[2][4], b[4][4];
            #pragma unroll
            for (int i = 0; i < 2; i++)
                ldsm_x4(a[i], As + (unsigned)((wm * 32 + i * 16 + lrow) * LDTH
                                              + kk * 16 + lcol) * 2);
            #pragma unroll
            for (int j = 0; j < 4; j++)
                ldsm_x4(b[j], Bs + (unsigned)((wn * 64 + j * 16 + lrow) * LDTH
                                              + kk * 16 + lcol) * 2);
            #pragma unroll
            for (int i = 0; i < 2; i++)
                #pragma unroll
                for (int j = 0; j < 4; j++) {
                    mma16816(acc[i][2 * j],     a[i], b[j][0], b[j][2]);
                    mma16816(acc[i][2 * j + 1], a[i], b[j][1], b[j][3]);
                }
        }
    }
    __syncthreads();

    // stage accumulators to smem for vectorized fused epilogue
    float* Cs = (float*)smem_raw;   // 128 x CLD
    const int tr = lid >> 2;
    const int tc = (lid & 3) << 1;
    #pragma unroll
    for (int i = 0; i < 2; i++)
        #pragma unroll
        for (int j = 0; j < 8; j++) {
            float* p = Cs + (wm * 32 + i * 16 + tr) * CLD + wn * 64 + j * 8 + tc;
            p[0] = acc[i][j][0];
            p[1] = acc[i][j][1];
            p[8 * CLD + 0] = acc[i][j][2];
            p[8 * CLD + 1] = acc[i][j][3];
        }
    __syncthreads();

    #pragma unroll 1
    for (int it = 0; it < 16; it++) {
        const int idx = tid + (it << 8);
        const int r = idx >> 5;
        const int c = (idx & 31) << 2;
        float4 v4 = *(const float4*)(Cs + r * CLD + c);
        float v[4] = { v4.x, v4.y, v4.z, v4.w };

        if (EPI == EPI_TOP2) {
            float v1 = -3.4e38f, v2 = -3.4e38f;
            int i1 = 0x7fffffff, i2 = 0x7fffffff;
            #pragma unroll
            for (int q = 0; q < 4; q++)
                top2_ins(v[q] * scale, bn + c + q, v1, i1, v2, i2);
            #pragma unroll
            for (int o = 16; o; o >>= 1) {
                float ov1 = __shfl_xor_sync(0xffffffffu, v1, o);
                float ov2 = __shfl_xor_sync(0xffffffffu, v2, o);
                int   oi1 = __shfl_xor_sync(0xffffffffu, i1, o);
                int   oi2 = __shfl_xor_sync(0xffffffffu, i2, o);
                top2_ins(ov1, oi1, v1, i1, v2, i2);
                top2_ins(ov2, oi2, v1, i1, v2, i2);
            }
            if (lid == 0) {
                const size_t cb = (size_t)(bm + r) * 64 + blockIdx.x * 2;
                aux[cb]  = v1;  aux[cb + 1]  = v2;
                auxi[cb] = i1;  auxi[cb + 1] = i2;
            }
            continue;
        }

        const size_t off = (size_t)(bm + r) * N + bn + c;
        if (EPI == EPI_GRU) {
            const int cg = bn + c;
            if (cg < DD) {
                float4 bv = *(const float4*)(bias + cg);
                float4 o4;
                o4.x = 1.0f / (1.0f + expf(-(v[0] + bv.x)));
                o4.y = 1.0f / (1.0f + expf(-(v[1] + bv.y)));
                o4.z = 1.0f / (1.0f + expf(-(v[2] + bv.z)));
                o4.w = 1.0f / (1.0f + expf(-(v[3] + bv.w)));
                *(float4*)((float*)Cout + (size_t)(bm + r) * DD + cg) = o4;
            } else {
                float4 bv = *(const float4*)(extraf + cg - DD);
                float4 o4 = { v[0] + bv.x, v[1] + bv.y, v[2] + bv.z, v[3] + bv.w };
                *(float4*)(aux + (size_t)(bm + r) * DD + cg - DD) = o4;
            }
            continue;
        }

        if (EPI == EPI_RESID) {
            float4 ev = *(const float4*)(extraf + off);
            v[0] += ev.x; v[1] += ev.y; v[2] += ev.z; v[3] += ev.w;
        } else if (EPI == EPI_SILUMUL) {
            uint2 eu = *(const uint2*)(extrah + off);
            __half2 e0 = *(__half2*)&eu.x;
            __half2 e1 = *(__half2*)&eu.y;
            float g0 = __low2float(e0), g1 = __high2float(e0);
            float g2 = __low2float(e1), g3 = __high2float(e1);
            v[0] *= g0 / (1.0f + expf(-g0));
            v[1] *= g1 / (1.0f + expf(-g1));
            v[2] *= g2 / (1.0f + expf(-g2));
            v[3] *= g3 / (1.0f + expf(-g3));
        }

        if (HOUT) {
            __half2 lo = __floats2half2_rn(v[0], v[1]);
            __half2 hi = __floats2half2_rn(v[2], v[3]);
            uint2 u = { *(unsigned*)&lo, *(unsigned*)&hi };
            *(uint2*)((__half*)Cout + off) = u;
        } else {
            float4 o4 = { v[0], v[1], v[2], v[3] };
            *(float4*)((float*)Cout + off) = o4;
        }
    }
}

// ---------------------------------------------------------------------------
// Fused: final top-2 over 64 candidates + softmax + gather (one block per row)
// ---------------------------------------------------------------------------
__global__ void __launch_bounds__(256) gather2_kernel(
    const float* __restrict__ cval, const int* __restrict__ cidx,
    const float* __restrict__ V, __half* __restrict__ out)
{
    const int row = blockIdx.x;
    const int tid = threadIdx.x;
    __shared__ float sw1, sw2;
    __shared__ int sidx1, sidx2;
    if (tid < 32) {
        const size_t base = (size_t)row * 64 + tid * 2;
        float v1 = cval[base], v2 = cval[base + 1];   // v1 >= v2 per epilogue
        int   i1 = cidx[base], i2 = cidx[base + 1];
        #pragma unroll
        for (int o = 16; o; o >>= 1) {
            float ov1 = __shfl_xor_sync(0xffffffffu, v1, o);
            float ov2 = __shfl_xor_sync(0xffffffffu, v2, o);
            int   oi1 = __shfl_xor_sync(0xffffffffu, i1, o);
            int   oi2 = __shfl_xor_sync(0xffffffffu, i2, o);
            top2_ins(ov1, oi1, v1, i1, v2, i2);
            top2_ins(ov2, oi2, v1, i1, v2, i2);
        }
        if (tid == 0) {
            const float e = expf(v2 - v1);
            const float inv = 1.0f / (1.0f + e);
            sw1 = inv; sw2 = e * inv; sidx1 = i1; sidx2 = i2;
        }
    }
    __syncthreads();
    const float w1 = sw1, w2 = sw2;
    const float4 a = ((const float4*)(V + (size_t)sidx1 * DD))[tid];
    const float4 b = ((const float4*)(V + (size_t)sidx2 * DD))[tid];
    __half2 lo = __floats2half2_rn(w1 * a.x + w2 * b.x, w1 * a.y + w2 * b.y);
    __half2 hi = __floats2half2_rn(w1 * a.z + w2 * b.z, w1 * a.w + w2 * b.w);
    uint2 u = { *(unsigned*)&lo, *(unsigned*)&hi };
    *(uint2*)(out + (size_t)row * DD + tid * 4) = u;
}

// ---------------------------------------------------------------------------
// MinGRU chunked scan (3 passes)
// ---------------------------------------------------------------------------
__global__ void __launch_bounds__(256) scan1_kernel(
    const float* __restrict__ z, const float* __restrict__ ht,
    float* __restrict__ Aout, float* __restrict__ Bout)
{
    const int tid = blockIdx.x * blockDim.x + threadIdx.x;
    const int d = tid & (DD - 1);
    const int r = tid / DD;
    const int c = r & (NC - 1);
    const int b = r / NC;
    const size_t base = ((size_t)b * TT + (size_t)c * CH) * DD + d;
    float Aa = 1.0f, Bb = 0.0f;
    #pragma unroll 4
    for (int t = 0; t < CH; t++) {
        const float zt = z[base + (size_t)t * DD];
        const float hh = ht[base + (size_t)t * DD];
        const float a = 1.0f - zt;
        Bb = a * Bb + zt * hh;
        Aa *= a;
    }
    Aout[tid] = Aa;
    Bout[tid] = Bb;
}

__global__ void __launch_bounds__(256) scan2_kernel(
    const float* __restrict__ h_prev, const float* __restrict__ Ain,
    const float* __restrict__ Bin, float* __restrict__ hstart,
    float* __restrict__ hlast)
{
    const int tid = blockIdx.x * blockDim.x + threadIdx.x;
    if (tid >= BB * DD) return;
    const int d = tid & (DD - 1);
    const int b = tid / DD;
    float h = h_prev[tid];
    for (int c = 0; c < NC; c++) {
        const size_t i = ((size_t)b * NC + c) * DD + d;
        hstart[i] = h;
        h = Ain[i] * h + Bin[i];
    }
    hlast[tid] = h;
}

__global__ void __launch_bounds__(256) scan3_kernel(
    const float* __restrict__ z, const float* __restrict__ ht,
    const float* __restrict__ hstart, float* __restrict__ xout)
{
    const int tid = blockIdx.x * blockDim.x + threadIdx.x;
    const int d = tid & (DD - 1);
    const int r = tid / DD;
    const int c = r & (NC - 1);
    const int b = r / NC;
    const size_t base = ((size_t)b * TT + (size_t)c * CH) * DD + d;
    float h = hstart[tid];
    for (int t = 0; t < CH; t++) {
        const float zt = z[base + (size_t)t * DD];
        const float hh = ht[base + (size_t)t * DD];
        h = (1.0f - zt) * h + zt * hh;
        xout[base + (size_t)t * DD] += h;
    }
}

// ---------------------------------------------------------------------------
// Launch sequence
// ---------------------------------------------------------------------------
extern "C" void kernel_launch(void* const* d_in, const int* in_sizes, int n_in,
                              void* d_out, int out_size)
{
    (void)in_sizes; (void)n_in; (void)out_size;
    const float* x        = (const float*)d_in[0];
    const float* h_prev   = (const float*)d_in[1];
    const float* norm1_w  = (const float*)d_in[2];
    const float* conv3_w  = (const float*)d_in[3];
    const float* conv7_w  = (const float*)d_in[4];
    const float* conv15_w = (const float*)d_in[5];
    const float* mix_w    = (const float*)d_in[6];
    const float* norm2_w  = (const float*)d_in[7];
    const float* Wz_w     = (const float*)d_in[8];
    const float* Wz_b     = (const float*)d_in[9];
    const float* Wh_w     = (const float*)d_in[10];
    const float* Wh_b     = (const float*)d_in[11];
    const float* norm3_w  = (const float*)d_in[12];
    const float* slot_k   = (const float*)d_in[13];
    const float* slot_v   = (const float*)d_in[14];
    const float* projq_w  = (const float*)d_in[15];
    const float* projout_w= (const float*)d_in[16];
    const float* norm4_w  = (const float*)d_in[17];
    const float* gate_w   = (const float*)d_in[18];
    const float* up_w     = (const float*)d_in[19];
    const float* down_w   = (const float*)d_in[20];
    float* out = (float*)d_out;

    float* scr = nullptr;
    cudaGetSymbolAddress((void**)&scr, g_scratch);
    __half* hp = nullptr;
    cudaGetSymbolAddress((void**)&hp, g_half);

    float* xn    = scr + OFF_XN;
    float* zbuf  = scr + OFF_Z;
    float* htbuf = scr + OFF_HT;
    float* scanA = scr + OFF_SA;
    float* scanB = scr + OFF_SB;
    float* hstart= scr + OFF_HS;

    __half* mixh  = hp + HOFF_MIX;
    __half* Wzh   = hp + HOFF_WZ;
    __half* pqh   = hp + HOFF_PQ;
    __half* poh   = hp + HOFF_PO;
    __half* skh   = hp + HOFF_SK;
    __half* gateh = hp + HOFF_GATE;
    __half* uph   = hp + HOFF_UP;
    __half* downh = hp + HOFF_DOWN;
    __half* convh = hp + HOFF_CONVH;
    __half* xnh   = hp + HOFF_XNH;
    __half* big2h = hp + HOFF_BIG2H;

    cudaFuncSetAttribute(tgemm_kernel<EPI_RESID,0>,   cudaFuncAttributeMaxDynamicSharedMemorySize, SMEM_BYTES);
    cudaFuncSetAttribute(tgemm_kernel<EPI_GRU,0>,     cudaFuncAttributeMaxDynamicSharedMemorySize, SMEM_BYTES);
    cudaFuncSetAttribute(tgemm_kernel<EPI_NONE,1>,    cudaFuncAttributeMaxDynamicSharedMemorySize, SMEM_BYTES);
    cudaFuncSetAttribute(tgemm_kernel<EPI_TOP2,0>,    cudaFuncAttributeMaxDynamicSharedMemorySize, SMEM_BYTES);
    cudaFuncSetAttribute(tgemm_kernel<EPI_SILUMUL,1>, cudaFuncAttributeMaxDynamicSharedMemorySize, SMEM_BYTES);

    const dim3 blk(256);
    const dim3 gD(DD / 128, BT / 128);
    const dim3 gG(2048 / 128, BT / 128);
    const dim3 gF(FF / 128, BT / 128);
    const dim3 gS(SS / 128, BT / 128);

    castall_kernel<<<(unsigned)(WTOT / 1024), blk>>>(
        mix_w, Wz_w, Wh_w, projq_w, projout_w, slot_k, gate_w, up_w, down_w, hp);

    // 1. conv block
    rmsnorm_kernel<0><<<BT, blk>>>(x, norm1_w, xn, nullptr);
    conv_kernel<<<(unsigned)(BTD / 256), blk>>>(xn, conv3_w, conv7_w, conv15_w, convh);
    tgemm_kernel<EPI_RESID,0><<<gD, blk, SMEM_BYTES>>>(
        convh, mixh, out, nullptr, x, nullptr, nullptr, nullptr, BT, DD, DD, 1.0f);

    // 2. MinGRU (fused Wz+Wh GEMM)
    rmsnorm_kernel<1><<<BT, blk>>>(out, norm2_w, nullptr, xnh);
    tgemm_kernel<EPI_GRU,0><<<gG, blk, SMEM_BYTES>>>(
        xnh, Wzh, zbuf, Wz_b, Wh_b, nullptr, htbuf, nullptr, BT, 2048, DD, 1.0f);
    scan1_kernel<<<(unsigned)(BDNC / 256), blk>>>(zbuf, htbuf, scanA, scanB);
    scan2_kernel<<<(BB * DD + 255) / 256, blk>>>(h_prev, scanA, scanB, hstart, out + BTD);
    scan3_kernel<<<(unsigned)(BDNC / 256), blk>>>(zbuf, htbuf, hstart, out);

    // 3. slot memory (top2 fused into scores GEMM epilogue; fused gather)
    rmsnorm_kernel<1><<<BT, blk>>>(out, norm3_w, nullptr, xnh);
    tgemm_kernel<EPI_NONE,1><<<gD, blk, SMEM_BYTES>>>(
        xnh, pqh, convh, nullptr, nullptr, nullptr, nullptr, nullptr, BT, DD, DD, 1.0f);
    tgemm_kernel<EPI_TOP2,0><<<gS, blk, SMEM_BYTES>>>(
        convh, skh, nullptr, nullptr, nullptr, nullptr, zbuf, (int*)htbuf,
        BT, SS, DD, 0.03125f);
    gather2_kernel<<<BT, blk>>>(zbuf, (int*)htbuf, slot_v, xnh);
    tgemm_kernel<EPI_RESID,0><<<gD, blk, SMEM_BYTES>>>(
        xnh, poh, out, nullptr, out, nullptr, nullptr, nullptr, BT, DD, DD, 1.0f);

    // 4. SwiGLU FFN
    rmsnorm_kernel<1><<<BT, blk>>>(out, norm4_w, nullptr, convh);
    tgemm_kernel<EPI_NONE,1><<<gF, blk, SMEM_BYTES>>>(
        convh, gateh, big2h, nullptr, nullptr, nullptr, nullptr, nullptr, BT, FF, DD, 1.0f);
    tgemm_kernel<EPI_SILUMUL,1><<<gF, blk, SMEM_BYTES>>>(
        convh, uph, big2h, nullptr, nullptr, big2h, nullptr, nullptr, BT, FF, DD, 1.0f);
    tgemm_kernel<EPI_RESID,0><<<gD, blk, SMEM_BYTES>>>(
        big2h, downh, out, nullptr, out, nullptr, nullptr, nullptr, BT, DD, FF, 1.0f);
}

// round 13
// speedup vs baseline: 1.1895x; 1.0100x over previous
#include <cuda_runtime.h>
#include <cuda_fp16.h>
#include <cstdint>
#include <math.h>

// ---------------------------------------------------------------------------
// Problem constants
// ---------------------------------------------------------------------------
#define BB 2
#define TT 4096
#define DD 1024
#define FF 4096
#define SS 4096
#define BT (BB * TT)          // 8192
#define BTD ((size_t)BT * DD) // 8,388,608
#define BTF ((size_t)BT * FF) // 33,554,432
#define NC 64
#define CH 64
#define BDNC ((size_t)BB * DD * NC) // 131072

#define MM ((size_t)1048576)
#define WTOT (21 * MM)

// fp32 scratch
__device__ float g_scratch[4 * BTD + 2 * BDNC + BDNC + (size_t)BT * 4 + BTF];

#define OFF_XN   ((size_t)0)
#define OFF_Z    (OFF_XN + BTD)
#define OFF_HT   (OFF_Z + BTD)
#define OFF_X1   (OFF_HT + BTD)
#define OFF_SA   (OFF_X1 + BTD)
#define OFF_SB   (OFF_SA + BDNC)
#define OFF_HS   (OFF_SB + BDNC)
#define OFF_TV   (OFF_HS + BDNC)
#define OFF_TI   (OFF_TV + (size_t)BT * 2)

// fp16 pool
#define HOFF_MIX   ((size_t)0)
#define HOFF_WZ    (1 * MM)
#define HOFF_WH    (2 * MM)
#define HOFF_PQ    (3 * MM)
#define HOFF_PO    (4 * MM)
#define HOFF_SK    (5 * MM)
#define HOFF_GATE  (9 * MM)
#define HOFF_UP    (13 * MM)
#define HOFF_DOWN  (17 * MM)
#define HOFF_CONVH (21 * MM)
#define HOFF_XNH   (HOFF_CONVH + BTD)
#define HOFF_BIG2H (HOFF_XNH + BTD)
__device__ __half g_half[HOFF_BIG2H + BTF];

// ---------------------------------------------------------------------------
// One mega-cast: all 9 weight tensors fp32 -> fp16 pool
// ---------------------------------------------------------------------------
__global__ void __launch_bounds__(256) castall_kernel(
    const float* __restrict__ mix, const float* __restrict__ wz,
    const float* __restrict__ wh,  const float* __restrict__ pq,
    const float* __restrict__ po,  const float* __restrict__ sk,
    const float* __restrict__ gate,const float* __restrict__ up,
    const float* __restrict__ down, __half* __restrict__ dst)
{
    const size_t i = ((size_t)blockIdx.x * blockDim.x + threadIdx.x) * 4;
    if (i >= WTOT) return;
    const float* src; size_t base;
    if (i < 5 * MM) {
        switch (i >> 20) {
            case 0: src = mix; base = 0;      break;
            case 1: src = wz;  base = 1 * MM; break;
            case 2: src = wh;  base = 2 * MM; break;
            case 3: src = pq;  base = 3 * MM; break;
            default: src = po; base = 4 * MM; break;
        }
    } else if (i < 9 * MM)  { src = sk;   base = 5 * MM; }
    else if (i < 13 * MM)   { src = gate; base = 9 * MM; }
    else if (i < 17 * MM)   { src = up;   base = 13 * MM; }
    else                    { src = down; base = 17 * MM; }
    float4 v = *(const float4*)(src + (i - base));
    __half2 lo = __floats2half2_rn(v.x, v.y);
    __half2 hi = __floats2half2_rn(v.z, v.w);
    uint2 o = { *(unsigned*)&lo, *(unsigned*)&hi };
    *(uint2*)(dst + i) = o;
}

// ---------------------------------------------------------------------------
// RMSNorm (fp32 or fp16 out)
// ---------------------------------------------------------------------------
template <int HALF_OUT>
__global__ void __launch_bounds__(256) rmsnorm_kernel(
    const float* __restrict__ x, const float* __restrict__ w,
    float* __restrict__ out, __half* __restrict__ outh)
{
    const size_t row = blockIdx.x;
    const int tid = threadIdx.x;
    const float4* xr = (const float4*)(x + row * DD);
    float4 a = xr[tid];
    float ss = a.x * a.x + a.y * a.y + a.z * a.z + a.w * a.w;
    #pragma unroll
    for (int o = 16; o; o >>= 1) ss += __shfl_xor_sync(0xffffffffu, ss, o);
    __shared__ float wss[8];
    if ((tid & 31) == 0) wss[tid >> 5] = ss;
    __syncthreads();
    if (tid < 8) {
        float v = wss[tid];
        #pragma unroll
        for (int o = 4; o; o >>= 1) v += __shfl_xor_sync(0xffu, v, o);
        if (tid == 0) wss[0] = v;
    }
    __syncthreads();
    const float inv = rsqrtf(wss[0] * (1.0f / DD) + 1e-6f);
    float4 wv = ((const float4*)w)[tid];
    float4 o4;
    o4.x = a.x * wv.x * inv;
    o4.y = a.y * wv.y * inv;
    o4.z = a.z * wv.z * inv;
    o4.w = a.w * wv.w * inv;
    if (HALF_OUT) {
        __half2 lo = __floats2half2_rn(o4.x, o4.y);
        __half2 hi = __floats2half2_rn(o4.z, o4.w);
        uint2 u = { *(unsigned*)&lo, *(unsigned*)&hi };
        *(uint2*)(outh + row * DD + tid * 4) = u;
    } else {
        ((float4*)(out + row * DD))[tid] = o4;
    }
}

// ---------------------------------------------------------------------------
// Multi-scale causal depthwise conv (fp16 in, fp16 out; fp32 accumulate)
// ---------------------------------------------------------------------------
__global__ void __launch_bounds__(256) conv_kernel(
    const __half* __restrict__ xn,
    const float* __restrict__ w3, const float* __restrict__ w7,
    const float* __restrict__ w15, __half* __restrict__ out)
{
    const size_t idx = (size_t)blockIdx.x * blockDim.x + threadIdx.x;
    const int d = (int)(idx & (DD - 1));
    const size_t bt = idx / DD;
    const int t = (int)(bt & (TT - 1));
    const int b = (int)(bt / TT);
    const __half* base = xn + (size_t)b * TT * DD + d;
    float acc = 0.0f;
    #pragma unroll
    for (int j = 0; j < 15; j++) {
        int tt = t - 14 + j;
        if (tt < 0) continue;
        float wsum = w15[d * 15 + j];
        if (j >= 8)  wsum += w7[d * 7 + (j - 8)];
        if (j >= 12) wsum += w3[d * 3 + (j - 12)];
        acc += wsum * __half2float(base[(size_t)tt * DD]);
    }
    out[idx] = __float2half_rn(acc);
}

// ---------------------------------------------------------------------------
// fp16 tensor GEMM: ldmatrix + mma.sync.m16n8k16.
// EXACT R8 mainloop: 128x128 CTA tile, 256 threads / 8 warps, warp tile
// 32x64, KTILE 64, 2-stage cp.async double buffer, two barriers per iter.
// ---------------------------------------------------------------------------
#define EPI_NONE    0
#define EPI_RESID   4
#define EPI_SILUMUL 5
#define EPI_GRU     6
#define EPI_TOP2    7

#define KTILE 64
#define LDTH 72
#define TILEH (128 * LDTH)
#define CLD 132
#define SMEM_BYTES (4 * TILEH * 2)   // 73728 B (>= 128*CLD*4 = 67584)

__device__ __forceinline__ void cpasync16(unsigned saddr, const void* gptr) {
    asm volatile("cp.async.cg.shared.global [%0], [%1], 16;\n"
                 :: "r"(saddr), "l"(gptr));
}
__device__ __forceinline__ void ldsm_x4(unsigned* r, unsigned saddr) {
    asm volatile("ldmatrix.sync.aligned.m8n8.x4.shared.b16 {%0,%1,%2,%3}, [%4];"
                 : "=r"(r[0]), "=r"(r[1]), "=r"(r[2]), "=r"(r[3]) : "r"(saddr));
}
__device__ __forceinline__ void mma16816(
    float* d, const unsigned* a, unsigned b0, unsigned b1)
{
    asm volatile(
        "mma.sync.aligned.m16n8k16.row.col.f32.f16.f16.f32 "
        "{%0,%1,%2,%3}, {%4,%5,%6,%7}, {%8,%9}, {%0,%1,%2,%3};"
        : "+f"(d[0]), "+f"(d[1]), "+f"(d[2]), "+f"(d[3])
        : "r"(a[0]), "r"(a[1]), "r"(a[2]), "r"(a[3]), "r"(b0), "r"(b1));
}
__device__ __forceinline__ void top2_ins(float v, int i,
    float& v1, int& i1, float& v2, int& i2)
{
    if (v > v1 || (v == v1 && i < i1)) { v2 = v1; i2 = i1; v1 = v; i1 = i; }
    else if (v > v2 || (v == v2 && i < i2)) { v2 = v; i2 = i; }
}

template <int EPI, int HOUT>
__global__ void __launch_bounds__(256, 2) tgemm_kernel(
    const __half* __restrict__ A, const __half* __restrict__ W,
    void* __restrict__ Cout, const float* __restrict__ bias,
    const float* __restrict__ extraf, const __half* __restrict__ extrah,
    float* __restrict__ aux, int* __restrict__ auxi,
    int M, int N, int K, float scale)
{
    extern __shared__ __align__(16) char smem_raw[];
    __half* smem = (__half*)smem_raw;
    const int tid  = threadIdx.x;
    const int warp = tid >> 5;
    const int lid  = tid & 31;
    const int wm   = warp & 3;      // 32-row slice
    const int wn   = warp >> 2;     // 64-col slice
    const int bm   = blockIdx.y * 128;
    const int bn   = blockIdx.x * 128;

    __half* Abuf[2] = { smem,             smem + TILEH };
    __half* Bbuf[2] = { smem + 2 * TILEH, smem + 3 * TILEH };
    const unsigned sA[2] = { (unsigned)__cvta_generic_to_shared(Abuf[0]),
                             (unsigned)__cvta_generic_to_shared(Abuf[1]) };
    const unsigned sB[2] = { (unsigned)__cvta_generic_to_shared(Bbuf[0]),
                             (unsigned)__cvta_generic_to_shared(Bbuf[1]) };

    float acc[2][8][4];
    #pragma unroll
    for (int i = 0; i < 2; i++)
        #pragma unroll
        for (int j = 0; j < 8; j++)
            #pragma unroll
            for (int q = 0; q < 4; q++) acc[i][j][q] = 0.0f;

    const int KT = K / KTILE;

    auto load_tile = [&](int kt, int b) {
        const __half* Ag = A + (size_t)bm * K + kt * KTILE;
        const __half* Bg = W + (size_t)bn * K + kt * KTILE;
        #pragma unroll
        for (int j = 0; j < 4; j++) {
            const int i   = tid + (j << 8);
            const int row = i >> 3;
            const int seg = (i & 7) << 3;
            cpasync16(sA[b] + (unsigned)(row * LDTH + seg) * 2,
                      Ag + (size_t)row * K + seg);
            cpasync16(sB[b] + (unsigned)(row * LDTH + seg) * 2,
                      Bg + (size_t)row * K + seg);
        }
    };

    const int lrow = lid & 15;
    const int lcol = (lid >> 4) << 3;

    load_tile(0, 0);
    asm volatile("cp.async.commit_group;\n");

    int buf = 0;
    for (int kt = 0; kt < KT; kt++) {
        if (kt + 1 < KT) {
            load_tile(kt + 1, buf ^ 1);
            asm volatile("cp.async.commit_group;\n");
            asm volatile("cp.async.wait_group 1;\n");
        } else {
            asm volatile("cp.async.wait_group 0;\n");
        }
        __syncthreads();

        const unsigned As = sA[buf];
        const unsigned Bs = sB[buf];
        #pragma unroll
        for (int kk = 0; kk < 4; kk++) {
            unsigned a[2][4], b[4][4];
            #pragma unroll
            for (int i = 0; i < 2; i++)
                ldsm_x4(a[i], As + (unsigned)((wm * 32 + i * 16 + lrow) * LDTH
                                              + kk * 16 + lcol) * 2);
            #pragma unroll
            for (int j = 0; j < 4; j++)
                ldsm_x4(b[j], Bs + (unsigned)((wn * 64 + j * 16 + lrow) * LDTH
                                              + kk * 16 + lcol) * 2);
            #pragma unroll
            for (int i = 0; i < 2; i++)
                #pragma unroll
                for (int j = 0; j < 4; j++) {
                    mma16816(acc[i][2 * j],     a[i], b[j][0], b[j][2]);
                    mma16816(acc[i][2 * j + 1], a[i], b[j][1], b[j][3]);
                }
        }
        buf ^= 1;
        __syncthreads();
    }

    // stage accumulators to smem for vectorized fused epilogue
    float* Cs = (float*)smem_raw;   // 128 x CLD
    const int tr = lid >> 2;
    const int tc = (lid & 3) << 1;
    #pragma unroll
    for (int i = 0; i < 2; i++)
        #pragma unroll
        for (int j = 0; j < 8; j++) {
            float* p = Cs + (wm * 32 + i * 16 + tr) * CLD + wn * 64 + j * 8 + tc;
            p[0] = acc[i][j][0];
            p[1] = acc[i][j][1];
            p[8 * CLD + 0] = acc[i][j][2];
            p[8 * CLD + 1] = acc[i][j][3];
        }
    __syncthreads();

    #pragma unroll 1
    for (int it = 0; it < 16; it++) {
        const int idx = tid + (it << 8);
        const int r = idx >> 5;
        const int c = (idx & 31) << 2;
        float4 v4 = *(const float4*)(Cs + r * CLD + c);
        float v[4] = { v4.x, v4.y, v4.z, v4.w };

        if (EPI == EPI_TOP2) {
            float v1 = -3.4e38f, v2 = -3.4e38f;
            int i1 = 0x7fffffff, i2 = 0x7fffffff;
            #pragma unroll
            for (int q = 0; q < 4; q++)
                top2_ins(v[q] * scale, bn + c + q, v1, i1, v2, i2);
            #pragma unroll
            for (int o = 16; o; o >>= 1) {
                float ov1 = __shfl_xor_sync(0xffffffffu, v1, o);
                float ov2 = __shfl_xor_sync(0xffffffffu, v2, o);
                int   oi1 = __shfl_xor_sync(0xffffffffu, i1, o);
                int   oi2 = __shfl_xor_sync(0xffffffffu, i2, o);
                top2_ins(ov1, oi1, v1, i1, v2, i2);
                top2_ins(ov2, oi2, v1, i1, v2, i2);
            }
            if (lid == 0) {
                const size_t cb = (size_t)(bm + r) * 64 + blockIdx.x * 2;
                aux[cb]  = v1;  aux[cb + 1]  = v2;
                auxi[cb] = i1;  auxi[cb + 1] = i2;
            }
            continue;
        }

        const size_t off = (size_t)(bm + r) * N + bn + c;
        if (EPI == EPI_GRU) {
            const int cg = bn + c;
            if (cg < DD) {
                float4 bv = *(const float4*)(bias + cg);
                float4 o4;
                o4.x = 1.0f / (1.0f + expf(-(v[0] + bv.x)));
                o4.y = 1.0f / (1.0f + expf(-(v[1] + bv.y)));
                o4.z = 1.0f / (1.0f + expf(-(v[2] + bv.z)));
                o4.w = 1.0f / (1.0f + expf(-(v[3] + bv.w)));
                *(float4*)((float*)Cout + (size_t)(bm + r) * DD + cg) = o4;
            } else {
                float4 bv = *(const float4*)(extraf + cg - DD);
                float4 o4 = { v[0] + bv.x, v[1] + bv.y, v[2] + bv.z, v[3] + bv.w };
                *(float4*)(aux + (size_t)(bm + r) * DD + cg - DD) = o4;
            }
            continue;
        }

        if (EPI == EPI_RESID) {
            float4 ev = *(const float4*)(extraf + off);
            v[0] += ev.x; v[1] += ev.y; v[2] += ev.z; v[3] += ev.w;
        } else if (EPI == EPI_SILUMUL) {
            uint2 eu = *(const uint2*)(extrah + off);
            __half2 e0 = *(__half2*)&eu.x;
            __half2 e1 = *(__half2*)&eu.y;
            float g0 = __low2float(e0), g1 = __high2float(e0);
            float g2 = __low2float(e1), g3 = __high2float(e1);
            v[0] *= g0 / (1.0f + expf(-g0));
            v[1] *= g1 / (1.0f + expf(-g1));
            v[2] *= g2 / (1.0f + expf(-g2));
            v[3] *= g3 / (1.0f + expf(-g3));
        }

        if (HOUT) {
            __half2 lo = __floats2half2_rn(v[0], v[1]);
            __half2 hi = __floats2half2_rn(v[2], v[3]);
            uint2 u = { *(unsigned*)&lo, *(unsigned*)&hi };
            *(uint2*)((__half*)Cout + off) = u;
        } else {
            float4 o4 = { v[0], v[1], v[2], v[3] };
            *(float4*)((float*)Cout + off) = o4;
        }
    }
}

// ---------------------------------------------------------------------------
// Fused: final top-2 over 64 candidates + softmax + gather (one block per row)
// ---------------------------------------------------------------------------
__global__ void __launch_bounds__(256) gather2_kernel(
    const float* __restrict__ cval, const int* __restrict__ cidx,
    const float* __restrict__ V, __half* __restrict__ out)
{
    const int row = blockIdx.x;
    const int tid = threadIdx.x;
    __shared__ float sw1, sw2;
    __shared__ int sidx1, sidx2;
    if (tid < 32) {
        const size_t base = (size_t)row * 64 + tid * 2;
        float v1 = cval[base], v2 = cval[base + 1];   // v1 >= v2 per epilogue
        int   i1 = cidx[base], i2 = cidx[base + 1];
        #pragma unroll
        for (int o = 16; o; o >>= 1) {
            float ov1 = __shfl_xor_sync(0xffffffffu, v1, o);
            float ov2 = __shfl_xor_sync(0xffffffffu, v2, o);
            int   oi1 = __shfl_xor_sync(0xffffffffu, i1, o);
            int   oi2 = __shfl_xor_sync(0xffffffffu, i2, o);
            top2_ins(ov1, oi1, v1, i1, v2, i2);
            top2_ins(ov2, oi2, v1, i1, v2, i2);
        }
        if (tid == 0) {
            const float e = expf(v2 - v1);
            const float inv = 1.0f / (1.0f + e);
            sw1 = inv; sw2 = e * inv; sidx1 = i1; sidx2 = i2;
        }
    }
    __syncthreads();
    const float w1 = sw1, w2 = sw2;
    const float4 a = ((const float4*)(V + (size_t)sidx1 * DD))[tid];
    const float4 b = ((const float4*)(V + (size_t)sidx2 * DD))[tid];
    __half2 lo = __floats2half2_rn(w1 * a.x + w2 * b.x, w1 * a.y + w2 * b.y);
    __half2 hi = __floats2half2_rn(w1 * a.z + w2 * b.z, w1 * a.w + w2 * b.w);
    uint2 u = { *(unsigned*)&lo, *(unsigned*)&hi };
    *(uint2*)(out + (size_t)row * DD + tid * 4) = u;
}

// ---------------------------------------------------------------------------
// MinGRU chunked scan (3 passes)
// ---------------------------------------------------------------------------
__global__ void __launch_bounds__(256) scan1_kernel(
    const float* __restrict__ z, const float* __restrict__ ht,
    float* __restrict__ Aout, float* __restrict__ Bout)
{
    const int tid = blockIdx.x * blockDim.x + threadIdx.x;
    const int d = tid & (DD - 1);
    const int r = tid / DD;
    const int c = r & (NC - 1);
    const int b = r / NC;
    const size_t base = ((size_t)b * TT + (size_t)c * CH) * DD + d;
    float Aa = 1.0f, Bb = 0.0f;
    #pragma unroll 4
    for (int t = 0; t < CH; t++) {
        const float zt = z[base + (size_t)t * DD];
        const float hh = ht[base + (size_t)t * DD];
        const float a = 1.0f - zt;
        Bb = a * Bb + zt * hh;
        Aa *= a;
    }
    Aout[tid] = Aa;
    Bout[tid] = Bb;
}

__global__ void __launch_bounds__(256) scan2_kernel(
    const float* __restrict__ h_prev, const float* __restrict__ Ain,
    const float* __restrict__ Bin, float* __restrict__ hstart,
    float* __restrict__ hlast)
{
    const int tid = blockIdx.x * blockDim.x + threadIdx.x;
    if (tid >= BB * DD) return;
    const int d = tid & (DD - 1);
    const int b = tid / DD;
    float h = h_prev[tid];
    for (int c = 0; c < NC; c++) {
        const size_t i = ((size_t)b * NC + c) * DD + d;
        hstart[i] = h;
        h = Ain[i] * h + Bin[i];
    }
    hlast[tid] = h;
}

__global__ void __launch_bounds__(256) scan3_kernel(
    const float* __restrict__ z, const float* __restrict__ ht,
    const float* __restrict__ hstart, float* __restrict__ xout)
{
    const int tid = blockIdx.x * blockDim.x + threadIdx.x;
    const int d = tid & (DD - 1);
    const int r = tid / DD;
    const int c = r & (NC - 1);
    const int b = r / NC;
    const size_t base = ((size_t)b * TT + (size_t)c * CH) * DD + d;
    float h = hstart[tid];
    for (int t = 0; t < CH; t++) {
        const float zt = z[base + (size_t)t * DD];
        const float hh = ht[base + (size_t)t * DD];
        h = (1.0f - zt) * h + zt * hh;
        xout[base + (size_t)t * DD] += h;
    }
}

// ---------------------------------------------------------------------------
// Launch sequence
// ---------------------------------------------------------------------------
extern "C" void kernel_launch(void* const* d_in, const int* in_sizes, int n_in,
                              void* d_out, int out_size)
{
    (void)in_sizes; (void)n_in; (void)out_size;
    const float* x        = (const float*)d_in[0];
    const float* h_prev   = (const float*)d_in[1];
    const float* norm1_w  = (const float*)d_in[2];
    const float* conv3_w  = (const float*)d_in[3];
    const float* conv7_w  = (const float*)d_in[4];
    const float* conv15_w = (const float*)d_in[5];
    const float* mix_w    = (const float*)d_in[6];
    const float* norm2_w  = (const float*)d_in[7];
    const float* Wz_w     = (const float*)d_in[8];
    const float* Wz_b     = (const float*)d_in[9];
    const float* Wh_w     = (const float*)d_in[10];
    const float* Wh_b     = (const float*)d_in[11];
    const float* norm3_w  = (const float*)d_in[12];
    const float* slot_k   = (const float*)d_in[13];
    const float* slot_v   = (const float*)d_in[14];
    const float* projq_w  = (const float*)d_in[15];
    const float* projout_w= (const float*)d_in[16];
    const float* norm4_w  = (const float*)d_in[17];
    const float* gate_w   = (const float*)d_in[18];
    const float* up_w     = (const float*)d_in[19];
    const float* down_w   = (const float*)d_in[20];
    float* out = (float*)d_out;

    float* scr = nullptr;
    cudaGetSymbolAddress((void**)&scr, g_scratch);
    __half* hp = nullptr;
    cudaGetSymbolAddress((void**)&hp, g_half);

    float* zbuf  = scr + OFF_Z;
    float* htbuf = scr + OFF_HT;
    float* scanA = scr + OFF_SA;
    float* scanB = scr + OFF_SB;
    float* hstart= scr + OFF_HS;

    __half* mixh  = hp + HOFF_MIX;
    __half* Wzh   = hp + HOFF_WZ;
    __half* pqh   = hp + HOFF_PQ;
    __half* poh   = hp + HOFF_PO;
    __half* skh   = hp + HOFF_SK;
    __half* gateh = hp + HOFF_GATE;
    __half* uph   = hp + HOFF_UP;
    __half* downh = hp + HOFF_DOWN;
    __half* convh = hp + HOFF_CONVH;
    __half* xnh   = hp + HOFF_XNH;
    __half* big2h = hp + HOFF_BIG2H;

    cudaFuncSetAttribute(tgemm_kernel<EPI_RESID,0>,   cudaFuncAttributeMaxDynamicSharedMemorySize, SMEM_BYTES);
    cudaFuncSetAttribute(tgemm_kernel<EPI_GRU,0>,     cudaFuncAttributeMaxDynamicSharedMemorySize, SMEM_BYTES);
    cudaFuncSetAttribute(tgemm_kernel<EPI_NONE,1>,    cudaFuncAttributeMaxDynamicSharedMemorySize, SMEM_BYTES);
    cudaFuncSetAttribute(tgemm_kernel<EPI_TOP2,0>,    cudaFuncAttributeMaxDynamicSharedMemorySize, SMEM_BYTES);
    cudaFuncSetAttribute(tgemm_kernel<EPI_SILUMUL,1>, cudaFuncAttributeMaxDynamicSharedMemorySize, SMEM_BYTES);

    const dim3 blk(256);
    const dim3 gD(DD / 128, BT / 128);
    const dim3 gG(2048 / 128, BT / 128);
    const dim3 gF(FF / 128, BT / 128);
    const dim3 gS(SS / 128, BT / 128);

    castall_kernel<<<(unsigned)(WTOT / 1024), blk>>>(
        mix_w, Wz_w, Wh_w, projq_w, projout_w, slot_k, gate_w, up_w, down_w, hp);

    // 1. conv block (rmsnorm -> fp16, conv fp16-in)
    rmsnorm_kernel<1><<<BT, blk>>>(x, norm1_w, nullptr, xnh);
    conv_kernel<<<(unsigned)(BTD / 256), blk>>>(xnh, conv3_w, conv7_w, conv15_w, convh);
    tgemm_kernel<EPI_RESID,0><<<gD, blk, SMEM_BYTES>>>(
        convh, mixh, out, nullptr, x, nullptr, nullptr, nullptr, BT, DD, DD, 1.0f);

    // 2. MinGRU (fused Wz+Wh GEMM)
    rmsnorm_kernel<1><<<BT, blk>>>(out, norm2_w, nullptr, xnh);
    tgemm_kernel<EPI_GRU,0><<<gG, blk, SMEM_BYTES>>>(
        xnh, Wzh, zbuf, Wz_b, Wh_b, nullptr, htbuf, nullptr, BT, 2048, DD, 1.0f);
    scan1_kernel<<<(unsigned)(BDNC / 256), blk>>>(zbuf, htbuf, scanA, scanB);
    scan2_kernel<<<(BB * DD + 255) / 256, blk>>>(h_prev, scanA, scanB, hstart, out + BTD);
    scan3_kernel<<<(unsigned)(BDNC / 256), blk>>>(zbuf, htbuf, hstart, out);

    // 3. slot memory (top2 fused into scores GEMM epilogue; fused gather)
    rmsnorm_kernel<1><<<BT, blk>>>(out, norm3_w, nullptr, xnh);
    tgemm_kernel<EPI_NONE,1><<<gD, blk, SMEM_BYTES>>>(
        xnh, pqh, convh, nullptr, nullptr, nullptr, nullptr, nullptr, BT, DD, DD, 1.0f);
    tgemm_kernel<EPI_TOP2,0><<<gS, blk, SMEM_BYTES>>>(
        convh, skh, nullptr, nullptr, nullptr, nullptr, zbuf, (int*)htbuf,
        BT, SS, DD, 0.03125f);
    gather2_kernel<<<BT, blk>>>(zbuf, (int*)htbuf, slot_v, xnh);
    tgemm_kernel<EPI_RESID,0><<<gD, blk, SMEM_BYTES>>>(
        xnh, poh, out, nullptr, out, nullptr, nullptr, nullptr, BT, DD, DD, 1.0f);

    // 4. SwiGLU FFN
    rmsnorm_kernel<1><<<BT, blk>>>(out, norm4_w, nullptr, convh);
    tgemm_kernel<EPI_NONE,1><<<gF, blk, SMEM_BYTES>>>(
        convh, gateh, big2h, nullptr, nullptr, nullptr, nullptr, nullptr, BT, FF, DD, 1.0f);
    tgemm_kernel<EPI_SILUMUL,1><<<gF, blk, SMEM_BYTES>>>(
        convh, uph, big2h, nullptr, nullptr, big2h, nullptr, nullptr, BT, FF, DD, 1.0f);
    tgemm_kernel<EPI_RESID,0><<<gD, blk, SMEM_BYTES>>>(
        big2h, downh, out, nullptr, out, nullptr, nullptr, nullptr, BT, DD, FF, 1.0f);
}

// round 15
// speedup vs baseline: 1.2311x; 1.0349x over previous
#include <cuda_runtime.h>
#include <cuda_fp16.h>
#include <cstdint>
#include <math.h>

// ---------------------------------------------------------------------------
// Problem constants
// ---------------------------------------------------------------------------
#define BB 2
#define TT 4096
#define DD 1024
#define FF 4096
#define SS 4096
#define BT (BB * TT)          // 8192
#define BTD ((size_t)BT * DD) // 8,388,608
#define BTF ((size_t)BT * FF) // 33,554,432
#define NC 64
#define CH 64
#define BDNC ((size_t)BB * DD * NC) // 131072

#define MM ((size_t)1048576)
#define CASTN (24 * MM)       // elements handled by castall

// fp32 scratch
__device__ float g_scratch[4 * BTD + 2 * BDNC + BDNC + (size_t)BT * 4 + BTF];

#define OFF_XN   ((size_t)0)
#define OFF_Z    (OFF_XN + BTD)
#define OFF_HT   (OFF_Z + BTD)
#define OFF_VP   (OFF_HT + BTD)      // V' fp32 [S, D] (4M floats of BTD slot)
#define OFF_SA   (OFF_VP + BTD)
#define OFF_SB   (OFF_SA + BDNC)
#define OFF_HS   (OFF_SB + BDNC)

// fp16 pool: mix | Wz | Wh | pqT | po | sk(4M) | sv(4M) | gate | up | down
#define HOFF_MIX   ((size_t)0)
#define HOFF_WZ    (1 * MM)
#define HOFF_WH    (2 * MM)
#define HOFF_PQT   (3 * MM)
#define HOFF_PO    (4 * MM)
#define HOFF_SK    (5 * MM)
#define HOFF_SV    (9 * MM)
#define HOFF_GATE  (13 * MM)
#define HOFF_UP    (17 * MM)
#define HOFF_DOWN  (21 * MM)
#define HOFF_CONVH (25 * MM)
#define HOFF_XNH   (HOFF_CONVH + BTD)
#define HOFF_BIG2H (HOFF_XNH + BTD)   // K' parks here until FFN reuses it
__device__ __half g_half[HOFF_BIG2H + BTF];

// ---------------------------------------------------------------------------
// Mega-cast: 9 tensors fp32 -> fp16 pool (pqT handled by transpose kernel)
// virtual index v in [0, 24M): mix|wz|wh then po,sk,sv,gate,up,down (dst=v+1M)
// ---------------------------------------------------------------------------
__global__ void __launch_bounds__(256) castall_kernel(
    const float* __restrict__ mix, const float* __restrict__ wz,
    const float* __restrict__ wh,  const float* __restrict__ po,
    const float* __restrict__ sk,  const float* __restrict__ sv,
    const float* __restrict__ gate,const float* __restrict__ up,
    const float* __restrict__ down, __half* __restrict__ dst)
{
    const size_t v = ((size_t)blockIdx.x * blockDim.x + threadIdx.x) * 4;
    if (v >= CASTN) return;
    const float* src; size_t sbase; size_t dbase;
    if (v < 3 * MM) {
        switch (v >> 20) {
            case 0: src = mix; sbase = 0;      break;
            case 1: src = wz;  sbase = 1 * MM; break;
            default: src = wh; sbase = 2 * MM; break;
        }
        dbase = sbase;
    } else if (v < 4 * MM)  { src = po;   sbase = 3 * MM;  dbase = 4 * MM; }
    else if (v < 8 * MM)    { src = sk;   sbase = 4 * MM;  dbase = 5 * MM; }
    else if (v < 12 * MM)   { src = sv;   sbase = 8 * MM;  dbase = 9 * MM; }
    else if (v < 16 * MM)   { src = gate; sbase = 12 * MM; dbase = 13 * MM; }
    else if (v < 20 * MM)   { src = up;   sbase = 16 * MM; dbase = 17 * MM; }
    else                    { src = down; sbase = 20 * MM; dbase = 21 * MM; }
    float4 w = *(const float4*)(src + (v - sbase));
    __half2 lo = __floats2half2_rn(w.x, w.y);
    __half2 hi = __floats2half2_rn(w.z, w.w);
    uint2 o = { *(unsigned*)&lo, *(unsigned*)&hi };
    *(uint2*)(dst + dbase + (v - sbase)) = o;
}

// ---------------------------------------------------------------------------
// Transpose-cast: projq fp32 [D,D] -> pqT fp16 with pqT[e,d] = projq[d,e]
// ---------------------------------------------------------------------------
__global__ void __launch_bounds__(256) transpose_cast_kernel(
    const float* __restrict__ src, __half* __restrict__ dst)
{
    __shared__ float tile[32][33];
    const int bx = blockIdx.x * 32;   // source col base (e)
    const int by = blockIdx.y * 32;   // source row base (d)
    const int tx = threadIdx.x & 31;
    const int ty = threadIdx.x >> 5;  // 0..7
    #pragma unroll
    for (int i = 0; i < 4; i++) {
        const int r = ty + i * 8;
        tile[r][tx] = src[(size_t)(by + r) * DD + bx + tx];
    }
    __syncthreads();
    #pragma unroll
    for (int i = 0; i < 4; i++) {
        const int r = ty + i * 8;     // output row within tile (e)
        dst[(size_t)(bx + r) * DD + by + tx] = __float2half_rn(tile[tx][r]);
    }
}

// ---------------------------------------------------------------------------
// RMSNorm (fp32 or fp16 out)
// ---------------------------------------------------------------------------
template <int HALF_OUT>
__global__ void __launch_bounds__(256) rmsnorm_kernel(
    const float* __restrict__ x, const float* __restrict__ w,
    float* __restrict__ out, __half* __restrict__ outh)
{
    const size_t row = blockIdx.x;
    const int tid = threadIdx.x;
    const float4* xr = (const float4*)(x + row * DD);
    float4 a = xr[tid];
    float ss = a.x * a.x + a.y * a.y + a.z * a.z + a.w * a.w;
    #pragma unroll
    for (int o = 16; o; o >>= 1) ss += __shfl_xor_sync(0xffffffffu, ss, o);
    __shared__ float wss[8];
    if ((tid & 31) == 0) wss[tid >> 5] = ss;
    __syncthreads();
    if (tid < 8) {
        float v = wss[tid];
        #pragma unroll
        for (int o = 4; o; o >>= 1) v += __shfl_xor_sync(0xffu, v, o);
        if (tid == 0) wss[0] = v;
    }
    __syncthreads();
    const float inv = rsqrtf(wss[0] * (1.0f / DD) + 1e-6f);
    float4 wv = ((const float4*)w)[tid];
    float4 o4;
    o4.x = a.x * wv.x * inv;
    o4.y = a.y * wv.y * inv;
    o4.z = a.z * wv.z * inv;
    o4.w = a.w * wv.w * inv;
    if (HALF_OUT) {
        __half2 lo = __floats2half2_rn(o4.x, o4.y);
        __half2 hi = __floats2half2_rn(o4.z, o4.w);
        uint2 u = { *(unsigned*)&lo, *(unsigned*)&hi };
        *(uint2*)(outh + row * DD + tid * 4) = u;
    } else {
        ((float4*)(out + row * DD))[tid] = o4;
    }
}

// ---------------------------------------------------------------------------
// Multi-scale causal depthwise conv (fp16 in, fp16 out; fp32 accumulate)
// ---------------------------------------------------------------------------
__global__ void __launch_bounds__(256) conv_kernel(
    const __half* __restrict__ xn,
    const float* __restrict__ w3, const float* __restrict__ w7,
    const float* __restrict__ w15, __half* __restrict__ out)
{
    const size_t idx = (size_t)blockIdx.x * blockDim.x + threadIdx.x;
    const int d = (int)(idx & (DD - 1));
    const size_t bt = idx / DD;
    const int t = (int)(bt & (TT - 1));
    const int b = (int)(bt / TT);
    const __half* base = xn + (size_t)b * TT * DD + d;
    float acc = 0.0f;
    #pragma unroll
    for (int j = 0; j < 15; j++) {
        int tt = t - 14 + j;
        if (tt < 0) continue;
        float wsum = w15[d * 15 + j];
        if (j >= 8)  wsum += w7[d * 7 + (j - 8)];
        if (j >= 12) wsum += w3[d * 3 + (j - 12)];
        acc += wsum * __half2float(base[(size_t)tt * DD]);
    }
    out[idx] = __float2half_rn(acc);
}

// ---------------------------------------------------------------------------
// fp16 tensor GEMM (EXACT R8 mainloop — frozen)
// ---------------------------------------------------------------------------
#define EPI_NONE    0
#define EPI_RESID   4
#define EPI_SILUMUL 5
#define EPI_GRU     6
#define EPI_TOP2    7

#define KTILE 64
#define LDTH 72
#define TILEH (128 * LDTH)
#define CLD 132
#define SMEM_BYTES (4 * TILEH * 2)   // 73728 B

__device__ __forceinline__ void cpasync16(unsigned saddr, const void* gptr) {
    asm volatile("cp.async.cg.shared.global [%0], [%1], 16;\n"
                 :: "r"(saddr), "l"(gptr));
}
__device__ __forceinline__ void ldsm_x4(unsigned* r, unsigned saddr) {
    asm volatile("ldmatrix.sync.aligned.m8n8.x4.shared.b16 {%0,%1,%2,%3}, [%4];"
                 : "=r"(r[0]), "=r"(r[1]), "=r"(r[2]), "=r"(r[3]) : "r"(saddr));
}
__device__ __forceinline__ void mma16816(
    float* d, const unsigned* a, unsigned b0, unsigned b1)
{
    asm volatile(
        "mma.sync.aligned.m16n8k16.row.col.f32.f16.f16.f32 "
        "{%0,%1,%2,%3}, {%4,%5,%6,%7}, {%8,%9}, {%0,%1,%2,%3};"
        : "+f"(d[0]), "+f"(d[1]), "+f"(d[2]), "+f"(d[3])
        : "r"(a[0]), "r"(a[1]), "r"(a[2]), "r"(a[3]), "r"(b0), "r"(b1));
}
__device__ __forceinline__ void top2_ins(float v, int i,
    float& v1, int& i1, float& v2, int& i2)
{
    if (v > v1 || (v == v1 && i < i1)) { v2 = v1; i2 = i1; v1 = v; i1 = i; }
    else if (v > v2 || (v == v2 && i < i2)) { v2 = v; i2 = i; }
}

template <int EPI, int HOUT>
__global__ void __launch_bounds__(256, 2) tgemm_kernel(
    const __half* __restrict__ A, const __half* __restrict__ W,
    void* __restrict__ Cout, const float* __restrict__ bias,
    const float* __restrict__ extraf, const __half* __restrict__ extrah,
    float* __restrict__ aux, int* __restrict__ auxi,
    int M, int N, int K, float scale)
{
    extern __shared__ __align__(16) char smem_raw[];
    __half* smem = (__half*)smem_raw;
    const int tid  = threadIdx.x;
    const int warp = tid >> 5;
    const int lid  = tid & 31;
    const int wm   = warp & 3;      // 32-row slice
    const int wn   = warp >> 2;     // 64-col slice
    const int bm   = blockIdx.y * 128;
    const int bn   = blockIdx.x * 128;

    __half* Abuf[2] = { smem,             smem + TILEH };
    __half* Bbuf[2] = { smem + 2 * TILEH, smem + 3 * TILEH };
    const unsigned sA[2] = { (unsigned)__cvta_generic_to_shared(Abuf[0]),
                             (unsigned)__cvta_generic_to_shared(Abuf[1]) };
    const unsigned sB[2] = { (unsigned)__cvta_generic_to_shared(Bbuf[0]),
                             (unsigned)__cvta_generic_to_shared(Bbuf[1]) };

    float acc[2][8][4];
    #pragma unroll
    for (int i = 0; i < 2; i++)
        #pragma unroll
        for (int j = 0; j < 8; j++)
            #pragma unroll
            for (int q = 0; q < 4; q++) acc[i][j][q] = 0.0f;

    const int KT = K / KTILE;

    auto load_tile = [&](int kt, int b) {
        const __half* Ag = A + (size_t)bm * K + kt * KTILE;
        const __half* Bg = W + (size_t)bn * K + kt * KTILE;
        #pragma unroll
        for (int j = 0; j < 4; j++) {
            const int i   = tid + (j << 8);
            const int row = i >> 3;
            const int seg = (i & 7) << 3;
            cpasync16(sA[b] + (unsigned)(row * LDTH + seg) * 2,
                      Ag + (size_t)row * K + seg);
            cpasync16(sB[b] + (unsigned)(row * LDTH + seg) * 2,
                      Bg + (size_t)row * K + seg);
        }
    };

    const int lrow = lid & 15;
    const int lcol = (lid >> 4) << 3;

    load_tile(0, 0);
    asm volatile("cp.async.commit_group;\n");

    int buf = 0;
    for (int kt = 0; kt < KT; kt++) {
        if (kt + 1 < KT) {
            load_tile(kt + 1, buf ^ 1);
            asm volatile("cp.async.commit_group;\n");
            asm volatile("cp.async.wait_group 1;\n");
        } else {
            asm volatile("cp.async.wait_group 0;\n");
        }
        __syncthreads();

        const unsigned As = sA[buf];
        const unsigned Bs = sB[buf];
        #pragma unroll
        for (int kk = 0; kk < 4; kk++) {
            unsigned a[2][4], b[4][4];
            #pragma unroll
            for (int i = 0; i < 2; i++)
                ldsm_x4(a[i], As + (unsigned)((wm * 32 + i * 16 + lrow) * LDTH
                                              + kk * 16 + lcol) * 2);
            #pragma unroll
            for (int j = 0; j < 4; j++)
                ldsm_x4(b[j], Bs + (unsigned)((wn * 64 + j * 16 + lrow) * LDTH
                                              + kk * 16 + lcol) * 2);
            #pragma unroll
            for (int i = 0; i < 2; i++)
                #pragma unroll
                for (int j = 0; j < 4; j++) {
                    mma16816(acc[i][2 * j],     a[i], b[j][0], b[j][2]);
                    mma16816(acc[i][2 * j + 1], a[i], b[j][1], b[j][3]);
                }
        }
        buf ^= 1;
        __syncthreads();
    }

    // stage accumulators to smem for vectorized fused epilogue
    float* Cs = (float*)smem_raw;   // 128 x CLD
    const int tr = lid >> 2;
    const int tc = (lid & 3) << 1;
    #pragma unroll
    for (int i = 0; i < 2; i++)
        #pragma unroll
        for (int j = 0; j < 8; j++) {
            float* p = Cs + (wm * 32 + i * 16 + tr) * CLD + wn * 64 + j * 8 + tc;
            p[0] = acc[i][j][0];
            p[1] = acc[i][j][1];
            p[8 * CLD + 0] = acc[i][j][2];
            p[8 * CLD + 1] = acc[i][j][3];
        }
    __syncthreads();

    #pragma unroll 1
    for (int it = 0; it < 16; it++) {
        const int idx = tid + (it << 8);
        const int r = idx >> 5;
        const int c = (idx & 31) << 2;
        float4 v4 = *(const float4*)(Cs + r * CLD + c);
        float v[4] = { v4.x, v4.y, v4.z, v4.w };

        if (EPI == EPI_TOP2) {
            float v1 = -3.4e38f, v2 = -3.4e38f;
            int i1 = 0x7fffffff, i2 = 0x7fffffff;
            #pragma unroll
            for (int q = 0; q < 4; q++)
                top2_ins(v[q] * scale, bn + c + q, v1, i1, v2, i2);
            #pragma unroll
            for (int o = 16; o; o >>= 1) {
                float ov1 = __shfl_xor_sync(0xffffffffu, v1, o);
                float ov2 = __shfl_xor_sync(0xffffffffu, v2, o);
                int   oi1 = __shfl_xor_sync(0xffffffffu, i1, o);
                int   oi2 = __shfl_xor_sync(0xffffffffu, i2, o);
                top2_ins(ov1, oi1, v1, i1, v2, i2);
                top2_ins(ov2, oi2, v1, i1, v2, i2);
            }
            if (lid == 0) {
                const size_t cb = (size_t)(bm + r) * 64 + blockIdx.x * 2;
                aux[cb]  = v1;  aux[cb + 1]  = v2;
                auxi[cb] = i1;  auxi[cb + 1] = i2;
            }
            continue;
        }

        const size_t off = (size_t)(bm + r) * N + bn + c;
        if (EPI == EPI_GRU) {
            const int cg = bn + c;
            if (cg < DD) {
                float4 bv = *(const float4*)(bias + cg);
                float4 o4;
                o4.x = 1.0f / (1.0f + expf(-(v[0] + bv.x)));
                o4.y = 1.0f / (1.0f + expf(-(v[1] + bv.y)));
                o4.z = 1.0f / (1.0f + expf(-(v[2] + bv.z)));
                o4.w = 1.0f / (1.0f + expf(-(v[3] + bv.w)));
                *(float4*)((float*)Cout + (size_t)(bm + r) * DD + cg) = o4;
            } else {
                float4 bv = *(const float4*)(extraf + cg - DD);
                float4 o4 = { v[0] + bv.x, v[1] + bv.y, v[2] + bv.z, v[3] + bv.w };
                *(float4*)(aux + (size_t)(bm + r) * DD + cg - DD) = o4;
            }
            continue;
        }

        if (EPI == EPI_RESID) {
            float4 ev = *(const float4*)(extraf + off);
            v[0] += ev.x; v[1] += ev.y; v[2] += ev.z; v[3] += ev.w;
        } else if (EPI == EPI_SILUMUL) {
            uint2 eu = *(const uint2*)(extrah + off);
            __half2 e0 = *(__half2*)&eu.x;
            __half2 e1 = *(__half2*)&eu.y;
            float g0 = __low2float(e0), g1 = __high2float(e0);
            float g2 = __low2float(e1), g3 = __high2float(e1);
            v[0] *= g0 / (1.0f + expf(-g0));
            v[1] *= g1 / (1.0f + expf(-g1));
            v[2] *= g2 / (1.0f + expf(-g2));
            v[3] *= g3 / (1.0f + expf(-g3));
        }

        if (HOUT) {
            __half2 lo = __floats2half2_rn(v[0], v[1]);
            __half2 hi = __floats2half2_rn(v[2], v[3]);
            uint2 u = { *(unsigned*)&lo, *(unsigned*)&hi };
            *(uint2*)((__half*)Cout + off) = u;
        } else {
            float4 o4 = { v[0], v[1], v[2], v[3] };
            *(float4*)((float*)Cout + off) = o4;
        }
    }
}

// ---------------------------------------------------------------------------
// Fused: final top-2 + softmax + gather from V' + residual add into out (fp32)
// ---------------------------------------------------------------------------
__global__ void __launch_bounds__(256) gather2_kernel(
    const float* __restrict__ cval, const int* __restrict__ cidx,
    const float* __restrict__ Vp, float* __restrict__ out)
{
    const int row = blockIdx.x;
    const int tid = threadIdx.x;
    __shared__ float sw1, sw2;
    __shared__ int sidx1, sidx2;
    if (tid < 32) {
        const size_t base = (size_t)row * 64 + tid * 2;
        float v1 = cval[base], v2 = cval[base + 1];   // v1 >= v2 per epilogue
        int   i1 = cidx[base], i2 = cidx[base + 1];
        #pragma unroll
        for (int o = 16; o; o >>= 1) {
            float ov1 = __shfl_xor_sync(0xffffffffu, v1, o);
            float ov2 = __shfl_xor_sync(0xffffffffu, v2, o);
            int   oi1 = __shfl_xor_sync(0xffffffffu, i1, o);
            int   oi2 = __shfl_xor_sync(0xffffffffu, i2, o);
            top2_ins(ov1, oi1, v1, i1, v2, i2);
            top2_ins(ov2, oi2, v1, i1, v2, i2);
        }
        if (tid == 0) {
            const float e = expf(v2 - v1);
            const float inv = 1.0f / (1.0f + e);
            sw1 = inv; sw2 = e * inv; sidx1 = i1; sidx2 = i2;
        }
    }
    __syncthreads();
    const float w1 = sw1, w2 = sw2;
    const float4 a = ((const float4*)(Vp + (size_t)sidx1 * DD))[tid];
    const float4 b = ((const float4*)(Vp + (size_t)sidx2 * DD))[tid];
    float4* op = (float4*)(out + (size_t)row * DD) + tid;
    float4 o = *op;
    o.x += w1 * a.x + w2 * b.x;
    o.y += w1 * a.y + w2 * b.y;
    o.z += w1 * a.z + w2 * b.z;
    o.w += w1 * a.w + w2 * b.w;
    *op = o;
}

// ---------------------------------------------------------------------------
// MinGRU chunked scan (3 passes)
// ---------------------------------------------------------------------------
__global__ void __launch_bounds__(256) scan1_kernel(
    const float* __restrict__ z, const float* __restrict__ ht,
    float* __restrict__ Aout, float* __restrict__ Bout)
{
    const int tid = blockIdx.x * blockDim.x + threadIdx.x;
    const int d = tid & (DD - 1);
    const int r = tid / DD;
    const int c = r & (NC - 1);
    const int b = r / NC;
    const size_t base = ((size_t)b * TT + (size_t)c * CH) * DD + d;
    float Aa = 1.0f, Bb = 0.0f;
    #pragma unroll 4
    for (int t = 0; t < CH; t++) {
        const float zt = z[base + (size_t)t * DD];
        const float hh = ht[base + (size_t)t * DD];
        const float a = 1.0f - zt;
        Bb = a * Bb + zt * hh;
        Aa *= a;
    }
    Aout[tid] = Aa;
    Bout[tid] = Bb;
}

__global__ void __launch_bounds__(256) scan2_kernel(
    const float* __restrict__ h_prev, const float* __restrict__ Ain,
    const float* __restrict__ Bin, float* __restrict__ hstart,
    float* __restrict__ hlast)
{
    const int tid = blockIdx.x * blockDim.x + threadIdx.x;
    if (tid >= BB * DD) return;
    const int d = tid & (DD - 1);
    const int b = tid / DD;
    float h = h_prev[tid];
    for (int c = 0; c < NC; c++) {
        const size_t i = ((size_t)b * NC + c) * DD + d;
        hstart[i] = h;
        h = Ain[i] * h + Bin[i];
    }
    hlast[tid] = h;
}

__global__ void __launch_bounds__(256) scan3_kernel(
    const float* __restrict__ z, const float* __restrict__ ht,
    const float* __restrict__ hstart, float* __restrict__ xout)
{
    const int tid = blockIdx.x * blockDim.x + threadIdx.x;
    const int d = tid & (DD - 1);
    const int r = tid / DD;
    const int c = r & (NC - 1);
    const int b = r / NC;
    const size_t base = ((size_t)b * TT + (size_t)c * CH) * DD + d;
    float h = hstart[tid];
    for (int t = 0; t < CH; t++) {
        const float zt = z[base + (size_t)t * DD];
        const float hh = ht[base + (size_t)t * DD];
        h = (1.0f - zt) * h + zt * hh;
        xout[base + (size_t)t * DD] += h;
    }
}

// ---------------------------------------------------------------------------
// Launch sequence
// ---------------------------------------------------------------------------
extern "C" void kernel_launch(void* const* d_in, const int* in_sizes, int n_in,
                              void* d_out, int out_size)
{
    (void)in_sizes; (void)n_in; (void)out_size;
    const float* x        = (const float*)d_in[0];
    const float* h_prev   = (const float*)d_in[1];
    const float* norm1_w  = (const float*)d_in[2];
    const float* conv3_w  = (const float*)d_in[3];
    const float* conv7_w  = (const float*)d_in[4];
    const float* conv15_w = (const float*)d_in[5];
    const float* mix_w    = (const float*)d_in[6];
    const float* norm2_w  = (const float*)d_in[7];
    const float* Wz_w     = (const float*)d_in[8];
    const float* Wz_b     = (const float*)d_in[9];
    const float* Wh_w     = (const float*)d_in[10];
    const float* Wh_b     = (const float*)d_in[11];
    const float* norm3_w  = (const float*)d_in[12];
    const float* slot_k   = (const float*)d_in[13];
    const float* slot_v   = (const float*)d_in[14];
    const float* projq_w  = (const float*)d_in[15];
    const float* projout_w= (const float*)d_in[16];
    const float* norm4_w  = (const float*)d_in[17];
    const float* gate_w   = (const float*)d_in[18];
    const float* up_w     = (const float*)d_in[19];
    const float* down_w   = (const float*)d_in[20];
    float* out = (float*)d_out;

    float* scr = nullptr;
    cudaGetSymbolAddress((void**)&scr, g_scratch);
    __half* hp = nullptr;
    cudaGetSymbolAddress((void**)&hp, g_half);

    float* zbuf  = scr + OFF_Z;
    float* htbuf = scr + OFF_HT;
    float* Vp    = scr + OFF_VP;     // V' fp32 [S, D]
    float* scanA = scr + OFF_SA;
    float* scanB = scr + OFF_SB;
    float* hstart= scr + OFF_HS;

    __half* mixh  = hp + HOFF_MIX;
    __half* Wzh   = hp + HOFF_WZ;
    __half* pqT   = hp + HOFF_PQT;
    __half* poh   = hp + HOFF_PO;
    __half* skh   = hp + HOFF_SK;
    __half* svh   = hp + HOFF_SV;
    __half* gateh = hp + HOFF_GATE;
    __half* uph   = hp + HOFF_UP;
    __half* downh = hp + HOFF_DOWN;
    __half* convh = hp + HOFF_CONVH;
    __half* xnh   = hp + HOFF_XNH;
    __half* big2h = hp + HOFF_BIG2H;  // holds K' until the FFN reuses it

    cudaFuncSetAttribute(tgemm_kernel<EPI_RESID,0>,   cudaFuncAttributeMaxDynamicSharedMemorySize, SMEM_BYTES);
    cudaFuncSetAttribute(tgemm_kernel<EPI_GRU,0>,     cudaFuncAttributeMaxDynamicSharedMemorySize, SMEM_BYTES);
    cudaFuncSetAttribute(tgemm_kernel<EPI_NONE,1>,    cudaFuncAttributeMaxDynamicSharedMemorySize, SMEM_BYTES);
    cudaFuncSetAttribute(tgemm_kernel<EPI_NONE,0>,    cudaFuncAttributeMaxDynamicSharedMemorySize, SMEM_BYTES);
    cudaFuncSetAttribute(tgemm_kernel<EPI_TOP2,0>,    cudaFuncAttributeMaxDynamicSharedMemorySize, SMEM_BYTES);
    cudaFuncSetAttribute(tgemm_kernel<EPI_SILUMUL,1>, cudaFuncAttributeMaxDynamicSharedMemorySize, SMEM_BYTES);

    const dim3 blk(256);
    const dim3 gD(DD / 128, BT / 128);      // 8 x 64
    const dim3 gG(2048 / 128, BT / 128);    // fused GRU GEMM
    const dim3 gF(FF / 128, BT / 128);      // 32 x 64
    const dim3 gS(SS / 128, BT / 128);
    const dim3 gP(DD / 128, SS / 128);      // precompute GEMMs: 8 x 32

    // 0. weight casts + slot-space precomputes (K' = sk@Wq, V' = sv@Po^T)
    castall_kernel<<<(unsigned)(CASTN / 1024), blk>>>(
        mix_w, Wz_w, Wh_w, projout_w, slot_k, slot_v, gate_w, up_w, down_w, hp);
    transpose_cast_kernel<<<dim3(32, 32), blk>>>(projq_w, pqT);
    tgemm_kernel<EPI_NONE,1><<<gP, blk, SMEM_BYTES>>>(
        skh, pqT, big2h, nullptr, nullptr, nullptr, nullptr, nullptr, SS, DD, DD, 1.0f);
    tgemm_kernel<EPI_NONE,0><<<gP, blk, SMEM_BYTES>>>(
        svh, poh, Vp, nullptr, nullptr, nullptr, nullptr, nullptr, SS, DD, DD, 1.0f);

    // 1. conv block
    rmsnorm_kernel<1><<<BT, blk>>>(x, norm1_w, nullptr, xnh);
    conv_kernel<<<(unsigned)(BTD / 256), blk>>>(xnh, conv3_w, conv7_w, conv15_w, convh);
    tgemm_kernel<EPI_RESID,0><<<gD, blk, SMEM_BYTES>>>(
        convh, mixh, out, nullptr, x, nullptr, nullptr, nullptr, BT, DD, DD, 1.0f);

    // 2. MinGRU (fused Wz+Wh GEMM)
    rmsnorm_kernel<1><<<BT, blk>>>(out, norm2_w, nullptr, xnh);
    tgemm_kernel<EPI_GRU,0><<<gG, blk, SMEM_BYTES>>>(
        xnh, Wzh, zbuf, Wz_b, Wh_b, nullptr, htbuf, nullptr, BT, 2048, DD, 1.0f);
    scan1_kernel<<<(unsigned)(BDNC / 256), blk>>>(zbuf, htbuf, scanA, scanB);
    scan2_kernel<<<(BB * DD + 255) / 256, blk>>>(h_prev, scanA, scanB, hstart, out + BTD);
    scan3_kernel<<<(unsigned)(BDNC / 256), blk>>>(zbuf, htbuf, hstart, out);

    // 3. slot memory: scores = xn @ K'^T directly (projq folded into K'),
    //    projout folded into V'; gather adds straight into the residual.
    rmsnorm_kernel<1><<<BT, blk>>>(out, norm3_w, nullptr, xnh);
    tgemm_kernel<EPI_TOP2,0><<<gS, blk, SMEM_BYTES>>>(
        xnh, big2h, nullptr, nullptr, nullptr, nullptr, zbuf, (int*)htbuf,
        BT, SS, DD, 0.03125f);
    gather2_kernel<<<BT, blk>>>(zbuf, (int*)htbuf, Vp, out);

    // 4. SwiGLU FFN (big2h is free again)
    rmsnorm_kernel<1><<<BT, blk>>>(out, norm4_w, nullptr, convh);
    tgemm_kernel<EPI_NONE,1><<<gF, blk, SMEM_BYTES>>>(
        convh, gateh, big2h, nullptr, nullptr, nullptr, nullptr, nullptr, BT, FF, DD, 1.0f);
    tgemm_kernel<EPI_SILUMUL,1><<<gF, blk, SMEM_BYTES>>>(
        convh, uph, big2h, nullptr, nullptr, big2h, nullptr, nullptr, BT, FF, DD, 1.0f);
    tgemm_kernel<EPI_RESID,0><<<gD, blk, SMEM_BYTES>>>(
        big2h, downh, out, nullptr, out, nullptr, nullptr, nullptr, BT, DD, FF, 1.0f);
}